// round 8
// baseline (speedup 1.0000x reference)
#include <cuda_runtime.h>
#include <cuda_fp16.h>
#include <math.h>
#include <stdint.h>

// ---- problem constants ----
#define Nb   2
#define T    4096
#define Dd   1024
#define H    8
#define E    4
#define Lw   32
#define TC   128
#define DK   64
#define NT   (Nb*T)       // 8192
#define PC   1568         // 32 G + 512 K + 512 V + 512 Q
#define RLEN (Lw + T)     // 4128

#define TQ   32
#define WW   63
#define SST  260

#define STAGES 3
// one pipeline stage = 256 rows x 64 halves (128 B) = 32768 bytes
#define STAGE_BYTES 32768
#define STAGE_U32   8192

// ---- device scratch ----
__device__ __half  g_Wh[(size_t)PC*Dd];     // fp16 weights (concat)
__device__ float   g_bias[PC];
__device__ __half  g_Xh[(size_t)NT*Dd];     // fp16 X
__device__ float   g_P[(size_t)NT*PC];
__device__ float   g_A[Nb*E*T];
__device__ float   g_gK[(size_t)Nb*E*T*DK];
__device__ float   g_gV[(size_t)Nb*E*T*DK];
__device__ float   g_recK[(size_t)Nb*E*RLEN*DK];
__device__ float   g_recV[(size_t)Nb*E*RLEN*DK];
__device__ __half  g_Yh[(size_t)NT*H*DK];   // fp16 attention output
__device__ __half  g_WoTh[(size_t)Dd*H*DK]; // fp16 w_O^T

// ============================================================
// helpers
// ============================================================
__device__ __forceinline__ void mma_f16(float4& c,
    uint32_t a0, uint32_t a1, uint32_t a2, uint32_t a3,
    uint32_t b0, uint32_t b1)
{
    asm volatile("mma.sync.aligned.m16n8k16.row.col.f32.f16.f16.f32 "
        "{%0,%1,%2,%3}, {%4,%5,%6,%7}, {%8,%9}, {%0,%1,%2,%3};"
        : "+f"(c.x), "+f"(c.y), "+f"(c.z), "+f"(c.w)
        : "r"(a0), "r"(a1), "r"(a2), "r"(a3), "r"(b0), "r"(b1));
}

__device__ __forceinline__ void cp16(uint32_t dst, const void* src, int sz) {
    asm volatile("cp.async.cg.shared.global [%0], [%1], 16, %2;"
                 :: "r"(dst), "l"(src), "r"(sz));
}
__device__ __forceinline__ void cp_commit() { asm volatile("cp.async.commit_group;"); }
__device__ __forceinline__ void cp_wait1()  { asm volatile("cp.async.wait_group 1;"); }

// ============================================================
// FP16 GEMM (NT): C[M][Nn] = A[M][K] * B[Nn][K]^T, fp32 accum.
// BM=128, BN=128, BK=64 per pipeline stage. 256 threads,
// 8 warps of 64x32. 3-stage cp.async pipeline, 2 CTAs/SM.
// Smem stage: rows [0,128)=A, [128,256)=B, 64 halves (128B) per row,
// stored as 8 16-byte chunks with chunk swizzle c ^= (row & 7)
// (conflict-free for both cp.async writes and fragment reads).
// Each K64 stage = two K32 sub-blocks; per sub-block a lane's uint4
// (4 half-pairs) feeds TWO m16n8k16 MMAs with a k-permutation that is
// identical for A and B, so the K-sum is exact under reassociation.
// ============================================================
template<bool ACT>
__global__ __launch_bounds__(256, 2) void mgemm(
    const __half* __restrict__ A, const __half* __restrict__ B,
    float* __restrict__ C, int M, int Nn, int K,
    const float* __restrict__ bias, int act_cols)
{
    extern __shared__ __align__(16) __half hsm[];

    int tid  = threadIdx.x;
    int bm   = blockIdx.y, bn = blockIdx.x;
    int warp = tid >> 5, lane = tid & 31;
    int wm   = (warp >> 2) * 64;          // 0,64
    int wn   = (warp & 3) * 32;           // 0,32,64,96
    int gid  = lane >> 2, tig = lane & 3;

    // staging: thread = one row (0..255), 8 cp16 chunks (128 B)
    int srow = tid;
    bool isA = srow < 128;
    int arow = bm*128 + srow;
    int brow = bn*128 + (srow - 128);
    int sz   = isA ? 16 : ((brow < Nn) ? 16 : 0);
    const __half* src = isA ? (A + (size_t)arow*K)
                            : (B + (size_t)(sz ? brow : 0)*K);

    uint32_t sbase = (uint32_t)__cvta_generic_to_shared(hsm);
    uint32_t rbase = sbase + srow*128;    // row base (bytes) in stage 0
    int rx = srow & 7;                    // swizzle key for this row

    auto stage = [&](int kt, int s) {
        uint32_t d = rbase + s*STAGE_BYTES;
        const __half* p = src + kt*64;
        #pragma unroll
        for (int c = 0; c < 8; ++c)
            cp16(d + (c ^ rx)*16, p + c*8, sz);
        cp_commit();
    };

    float4 acc[4][4];
    #pragma unroll
    for (int i = 0; i < 4; ++i)
        #pragma unroll
        for (int j = 0; j < 4; ++j) acc[i][j] = make_float4(0.f,0.f,0.f,0.f);

    int nk = K / 64;
    stage(0, 0);
    stage(1, 1);

    const uint32_t* Hs = (const uint32_t*)hsm;   // uint32 (half2) view

    for (int kt = 0; kt < nk; ++kt) {
        cp_wait1();
        __syncthreads();

        int buf = kt % STAGES;
        const uint32_t* bufp = Hs + buf*STAGE_U32;

        #pragma unroll
        for (int sub = 0; sub < 2; ++sub) {
            // fragment loads: row pitch = 32 u32; chunk = sub*4 + tig, swizzled
            uint4 alo[4], ahi[4], bf[4];
            #pragma unroll
            for (int mf = 0; mf < 4; ++mf) {
                int r0 = wm + mf*16 + gid;
                int r1 = r0 + 8;
                alo[mf] = *(const uint4*)&bufp[r0*32 + (((sub<<2)|tig) ^ (r0 & 7))*4];
                ahi[mf] = *(const uint4*)&bufp[r1*32 + (((sub<<2)|tig) ^ (r1 & 7))*4];
            }
            #pragma unroll
            for (int nf = 0; nf < 4; ++nf) {
                int r = 128 + wn + nf*8 + gid;
                bf[nf] = *(const uint4*)&bufp[r*32 + (((sub<<2)|tig) ^ (r & 7))*4];
            }

            #pragma unroll
            for (int mf = 0; mf < 4; ++mf)
                #pragma unroll
                for (int nf = 0; nf < 4; ++nf) {
                    mma_f16(acc[mf][nf], alo[mf].x, ahi[mf].x, alo[mf].y, ahi[mf].y,
                                         bf[nf].x, bf[nf].y);
                    mma_f16(acc[mf][nf], alo[mf].z, ahi[mf].z, alo[mf].w, ahi[mf].w,
                                         bf[nf].z, bf[nf].w);
                }
        }

        int kn = kt + (STAGES - 1);
        if (kn < nk) stage(kn, kn % STAGES);
        else cp_commit();
    }

    // epilogue: (c.x,c.y) -> (row gid, col 2t,2t+1); (c.z,c.w) -> row gid+8
    #pragma unroll
    for (int mf = 0; mf < 4; ++mf) {
        int row = bm*128 + wm + mf*16 + gid;
        #pragma unroll
        for (int nf = 0; nf < 4; ++nf) {
            int col = bn*128 + wn + nf*8 + tig*2;
            if (col < Nn) {
                float4 v = acc[mf][nf];
                if (ACT && col < act_cols) {
                    v.x = 1.f/(1.f + __expf(-(v.x + bias[col])));
                    v.y = 1.f/(1.f + __expf(-(v.y + bias[col+1])));
                    v.z = 1.f/(1.f + __expf(-(v.z + bias[col])));
                    v.w = 1.f/(1.f + __expf(-(v.w + bias[col+1])));
                }
                *(float2*)(C + (size_t)row*Nn + col)     = make_float2(v.x, v.y);
                *(float2*)(C + (size_t)(row+8)*Nn + col) = make_float2(v.z, v.w);
            }
        }
    }
}

// ============================================================
// fused weight pack + fp16 convert
// ============================================================
__global__ void pack_weights(const float4* __restrict__ wG,
                             const float4* __restrict__ wK,
                             const float4* __restrict__ wV,
                             const float4* __restrict__ wQ)
{
    int i = blockIdx.x*blockDim.x + threadIdx.x;   // float4 index
    if (i >= PC*Dd/4) return;
    int row = i / (Dd/4);
    int c4  = i - row*(Dd/4);
    float4 v;
    if (row < 32)        v = wG[row*(Dd/4) + c4];
    else if (row < 544)  v = wK[(row-32)*(Dd/4) + c4];
    else if (row < 1056) v = wV[(row-544)*(Dd/4) + c4];
    else                 v = wQ[(row-1056)*(Dd/4) + c4];
    __half2* o = (__half2*)(g_Wh + (size_t)i*4);
    o[0] = __floats2half2_rn(v.x, v.y);
    o[1] = __floats2half2_rn(v.z, v.w);
}

__global__ void cvt_x(const float4* __restrict__ X, int n4)
{
    int i = blockIdx.x*blockDim.x + threadIdx.x;
    if (i < n4) {
        float4 v = X[i];
        __half2* o = (__half2*)(g_Xh + (size_t)i*4);
        o[0] = __floats2half2_rn(v.x, v.y);
        o[1] = __floats2half2_rn(v.z, v.w);
    }
}

// ============================================================
// Gate combine
// ============================================================
__global__ __launch_bounds__(256) void gate_combine()
{
    int row = blockIdx.x;
    int n = row / T, t = row - n*T;
    __shared__ float sG[H*E];
    int tid = threadIdx.x;
    const float* Pr = g_P + (size_t)row*PC;
    if (tid < H*E) sG[tid] = Pr[tid];
    __syncthreads();
    if (tid < E) {
        float s = 0.f;
        #pragma unroll
        for (int h = 0; h < H; ++h) s += sG[h*E + tid];
        g_A[(n*E + tid)*T + t] = 1.f - fminf(s, 1.f);
    }
    int e = tid >> 6, d = tid & 63;
    float sk = 0.f, sv = 0.f;
    #pragma unroll
    for (int h = 0; h < H; ++h) {
        float g = sG[h*E + e];
        sk = fmaf(g, Pr[32  + h*64 + d], sk);
        sv = fmaf(g, Pr[544 + h*64 + d], sv);
    }
    size_t o = ((size_t)(n*E + e)*T + t)*DK + d;
    g_gK[o] = sk;
    g_gV[o] = sv;
}

// ============================================================
// Scan (pipelined)
// ============================================================
__global__ __launch_bounds__(128) void scan_kernel(
    const float* __restrict__ initK, const float* __restrict__ initV)
{
    __shared__ float sa[TC];
    int b = blockIdx.x;
    int l = b % Lw, e = (b / Lw) % E, n = b / (Lw*E);
    int tid = threadIdx.x;
    bool isV = tid >= 64;
    int d = tid & 63;
    const float* init = isV ? initV : initK;
    const float* g    = isV ? g_gV  : g_gK;
    float*       rec  = isV ? g_recV : g_recK;

    size_t base = (size_t)(n*E + e);
    int t0 = l*TC;
    const float* Arow = g_A + base*T + t0;
    if (tid < TC) sa[tid] = Arow[tid];
    __syncthreads();

    float st = init[(e*Lw + l)*DK + d];
    rec[(base*RLEN + l)*DK + d] = st;
    const float* grow   = g   + (base*T   + t0)*(size_t)DK + d;
    float*       recrow = rec + (base*RLEN + Lw + t0)*(size_t)DK + d;

    float gbuf[8];
    #pragma unroll
    for (int j = 0; j < 8; ++j) gbuf[j] = grow[(size_t)j*DK];

    for (int c0 = 0; c0 < TC; c0 += 8) {
        float gn[8];
        if (c0 + 8 < TC) {
            #pragma unroll
            for (int j = 0; j < 8; ++j) gn[j] = grow[(size_t)(c0+8+j)*DK];
        }
        #pragma unroll
        for (int j = 0; j < 8; ++j) {
            st = fmaf(sa[c0+j], st, gbuf[j]);
            recrow[(size_t)(c0+j)*DK] = st;
        }
        #pragma unroll
        for (int j = 0; j < 8; ++j) gbuf[j] = gn[j];
    }
}

// ============================================================
// Attention: online softmax; writes Y directly as fp16
// ============================================================
extern __shared__ float sm_att[];

__global__ __launch_bounds__(256, 1) void attention_kernel()
{
    float* Ks = sm_att;
    float* Vs = sm_att + WW*SST;
    int bid = blockIdx.x;
    int n    = bid / (T/TQ);
    int tile = bid % (T/TQ);
    int t0 = tile*TQ;
    int tid = threadIdx.x;

    for (int i = tid; i < WW*E*16; i += 256) {
        int w   = i >> 6;
        int rem = i & 63;
        int e = rem >> 4, d4 = rem & 15;
        size_t go = (((size_t)(n*E + e))*RLEN + (1 + t0 + w))*DK + d4*4;
        float4 kv = *(const float4*)(g_recK + go);
        float4 vv = *(const float4*)(g_recV + go);
        int so = w*SST + e*64 + d4*4;
        *(float4*)(Ks + so) = kv;
        *(float4*)(Vs + so) = vv;
    }
    __syncthreads();

    int h = tid & 7, tq = tid >> 3;
    int t = t0 + tq;
    float4 q[16];
    const float* Qp = g_P + (size_t)(n*T + t)*PC + 1056 + h*64;
    #pragma unroll
    for (int i = 0; i < 16; ++i) q[i] = *(const float4*)(Qp + i*4);

    float m = -1e30f, sum = 0.f;
    float4 acc[16];
    #pragma unroll
    for (int i = 0; i < 16; ++i) acc[i] = make_float4(0.f,0.f,0.f,0.f);

    for (int e = 0; e < E; ++e) {
        for (int l = 0; l < Lw; ++l) {
            const float* kp = Ks + (tq + l)*SST + e*64;
            float s = 0.f;
            #pragma unroll
            for (int i = 0; i < 16; ++i) {
                float4 k4 = *(const float4*)(kp + i*4);
                s = fmaf(q[i].x,k4.x, fmaf(q[i].y,k4.y,
                    fmaf(q[i].z,k4.z, fmaf(q[i].w,k4.w, s))));
            }
            s *= 0.125f;
            if (s > m) {
                float f = __expf(m - s);
                sum *= f;
                #pragma unroll
                for (int i = 0; i < 16; ++i) {
                    acc[i].x *= f; acc[i].y *= f; acc[i].z *= f; acc[i].w *= f;
                }
                m = s;
            }
            float p = __expf(s - m);
            sum += p;
            const float* vp = Vs + (tq + l)*SST + e*64;
            #pragma unroll
            for (int i = 0; i < 16; ++i) {
                float4 v4 = *(const float4*)(vp + i*4);
                acc[i].x = fmaf(p, v4.x, acc[i].x);
                acc[i].y = fmaf(p, v4.y, acc[i].y);
                acc[i].z = fmaf(p, v4.z, acc[i].z);
                acc[i].w = fmaf(p, v4.w, acc[i].w);
            }
        }
    }

    float inv = 1.f / sum;
    __half2* Yp = (__half2*)(g_Yh + (size_t)(n*T + t)*(H*DK) + h*64);
    #pragma unroll
    for (int i = 0; i < 16; ++i) {
        Yp[i*2]   = __floats2half2_rn(acc[i].x*inv, acc[i].y*inv);
        Yp[i*2+1] = __floats2half2_rn(acc[i].z*inv, acc[i].w*inv);
    }
}

// ============================================================
// w_O transpose: (512,1024) -> (1024,512), fp16 output
// ============================================================
__global__ void transpose_wo(const float* __restrict__ src)
{
    __shared__ float tile[32][33];
    int tx = threadIdx.x, ty = threadIdx.y;
    int x = blockIdx.x*32 + tx;
    int y = blockIdx.y*32 + ty;
    #pragma unroll
    for (int i = 0; i < 32; i += 8)
        tile[ty+i][tx] = src[(size_t)(y+i)*Dd + x];
    __syncthreads();
    int x2 = blockIdx.y*32 + tx;
    int y2 = blockIdx.x*32 + ty;
    #pragma unroll
    for (int i = 0; i < 32; i += 8)
        g_WoTh[(size_t)(y2+i)*(H*DK) + x2] = __float2half_rn(tile[tx][ty+i]);
}

// ============================================================
extern "C" void kernel_launch(void* const* d_in, const int* in_sizes, int n_in,
                              void* d_out, int out_size)
{
    const float* X  = (const float*)d_in[0];
    const float* wG = (const float*)d_in[1];
    const float* bG = (const float*)d_in[2];
    const float* wK = (const float*)d_in[3];
    const float* wV = (const float*)d_in[4];
    const float* wQ = (const float*)d_in[5];
    const float* wO = (const float*)d_in[6];
    const float* iK = (const float*)d_in[7];
    const float* iV = (const float*)d_in[8];
    float* out = (float*)d_out;

    cudaMemcpyToSymbolAsync(g_bias, bG, 32*sizeof(float), 0, cudaMemcpyDeviceToDevice, 0);

    float *dBias, *dP;
    __half *dXh, *dWh, *dYh, *dWoTh;
    cudaGetSymbolAddress((void**)&dWh,   g_Wh);
    cudaGetSymbolAddress((void**)&dBias, g_bias);
    cudaGetSymbolAddress((void**)&dP,    g_P);
    cudaGetSymbolAddress((void**)&dYh,   g_Yh);
    cudaGetSymbolAddress((void**)&dWoTh, g_WoTh);
    cudaGetSymbolAddress((void**)&dXh,   g_Xh);

    // pack + convert operands to fp16
    pack_weights<<<(PC*Dd/4 + 255)/256, 256>>>(
        (const float4*)wG, (const float4*)wK, (const float4*)wV, (const float4*)wQ);
    cvt_x<<<((NT*Dd/4) + 255)/256, 256>>>((const float4*)X, NT*Dd/4);
    transpose_wo<<<dim3(Dd/32, (H*DK)/32), dim3(32,8)>>>(wO);

    int gsmem = STAGES*STAGE_BYTES;   // 98304 B
    cudaFuncSetAttribute(mgemm<true>,  cudaFuncAttributeMaxDynamicSharedMemorySize, gsmem);
    cudaFuncSetAttribute(mgemm<false>, cudaFuncAttributeMaxDynamicSharedMemorySize, gsmem);

    // 1) fused projection GEMM (fp16 tensor cores, fp32 accum)
    mgemm<true><<<dim3((PC+127)/128, NT/128), 256, gsmem>>>(
        dXh, dWh, dP, NT, PC, Dd, dBias, 32);

    // 2) gates
    gate_combine<<<NT, 256>>>();

    // 3) scans
    scan_kernel<<<Nb*E*Lw, 128>>>(iK, iV);

    // 4) attention
    int smem_bytes = 2*WW*SST*sizeof(float);
    cudaFuncSetAttribute(attention_kernel, cudaFuncAttributeMaxDynamicSharedMemorySize, smem_bytes);
    attention_kernel<<<Nb*(T/TQ), 256, smem_bytes>>>();

    // 5) output projection
    mgemm<false><<<dim3(Dd/128, NT/128), 256, gsmem>>>(
        dYh, dWoTh, out, NT, Dd, H*DK, nullptr, 0);
}

// round 9
// speedup vs baseline: 1.2902x; 1.2902x over previous
#include <cuda_runtime.h>
#include <cuda_fp16.h>
#include <math.h>
#include <stdint.h>

// ---- problem constants ----
#define Nb   2
#define T    4096
#define Dd   1024
#define H    8
#define E    4
#define Lw   32
#define TC   128
#define DK   64
#define NT   (Nb*T)       // 8192
#define PC   1568         // 32 G + 512 K + 512 V + 512 Q
#define RLEN (Lw + T)     // 4128

#define TQ   32
#define WW   63
#define SST  260

#define STAGES 3
// one pipeline stage = 384 rows (256 A + 128 B) x 32 halves (64 B) = 24576 B
#define STAGE_BYTES 24576
#define STAGE_U32   6144

// ---- device scratch ----
__device__ __half  g_Wh[(size_t)PC*Dd];     // fp16 weights (concat)
__device__ float   g_bias[PC];
__device__ __half  g_Xh[(size_t)NT*Dd];     // fp16 X
__device__ float   g_P[(size_t)NT*PC];
__device__ float   g_A[Nb*E*T];
__device__ float   g_gK[(size_t)Nb*E*T*DK];
__device__ float   g_gV[(size_t)Nb*E*T*DK];
__device__ float   g_recK[(size_t)Nb*E*RLEN*DK];
__device__ float   g_recV[(size_t)Nb*E*RLEN*DK];
__device__ __half  g_Yh[(size_t)NT*H*DK];   // fp16 attention output
__device__ __half  g_WoTh[(size_t)Dd*H*DK]; // fp16 w_O^T

// ============================================================
// helpers
// ============================================================
__device__ __forceinline__ void mma_f16(float4& c,
    uint32_t a0, uint32_t a1, uint32_t a2, uint32_t a3,
    uint32_t b0, uint32_t b1)
{
    asm volatile("mma.sync.aligned.m16n8k16.row.col.f32.f16.f16.f32 "
        "{%0,%1,%2,%3}, {%4,%5,%6,%7}, {%8,%9}, {%0,%1,%2,%3};"
        : "+f"(c.x), "+f"(c.y), "+f"(c.z), "+f"(c.w)
        : "r"(a0), "r"(a1), "r"(a2), "r"(a3), "r"(b0), "r"(b1));
}

__device__ __forceinline__ void cp16(uint32_t dst, const void* src, int sz) {
    asm volatile("cp.async.cg.shared.global [%0], [%1], 16, %2;"
                 :: "r"(dst), "l"(src), "r"(sz));
}
__device__ __forceinline__ void cp_commit() { asm volatile("cp.async.commit_group;"); }
__device__ __forceinline__ void cp_wait1()  { asm volatile("cp.async.wait_group 1;"); }

// ============================================================
// FP16 GEMM (NT): C[M][Nn] = A[M][K] * B[Nn][K]^T, fp32 accum.
// BM=256, BN=128, BK=32 per stage. 256 threads, 8 warps of 64x64
// (4x2 warp grid). 3-stage cp.async pipeline, 1 CTA/SM.
// Smem stage: rows [0,256)=A, [256,384)=B, 32 halves (64 B) per row.
// Fragment loads: uint4 per lane -> 4 half-pairs feeding TWO
// m16n8k16 MMAs; (lane,slot)->k-pair permutation identical for A
// and B, so the K-sum is exact under reassociation.
// ============================================================
template<bool ACT>
__global__ __launch_bounds__(256, 1) void mgemm(
    const __half* __restrict__ A, const __half* __restrict__ B,
    float* __restrict__ C, int M, int Nn, int K,
    const float* __restrict__ bias, int act_cols)
{
    extern __shared__ __align__(16) __half hsm[];

    int tid  = threadIdx.x;
    int bm   = blockIdx.y, bn = blockIdx.x;
    int warp = tid >> 5, lane = tid & 31;
    int wm   = (warp >> 1) * 64;          // 0,64,128,192
    int wn   = (warp & 1) * 64;           // 0,64
    int gid  = lane >> 2, tig = lane & 3;

    uint32_t sbase = (uint32_t)__cvta_generic_to_shared(hsm);

    // staging: 1536 16B chunks per stage, 6 per thread (precomputed)
    const __half* srcp[6];
    uint32_t dsto[6];
    int szs[6];
    #pragma unroll
    for (int j = 0; j < 6; ++j) {
        int i = j*256 + tid;              // chunk index 0..1535
        int row = i >> 2, c = i & 3;      // 4 chunks (64 B) per row
        bool isA = row < 256;
        int g  = isA ? (bm*256 + row) : (bn*128 + (row - 256));
        int sz = isA ? 16 : ((g < Nn) ? 16 : 0);
        srcp[j] = (isA ? A + (size_t)g*K
                       : B + (size_t)(sz ? g : 0)*K) + c*8;
        dsto[j] = row*64 + c*16;
        szs[j]  = sz;
    }

    auto stage = [&](int kt, int s) {
        uint32_t d = sbase + s*STAGE_BYTES;
        #pragma unroll
        for (int j = 0; j < 6; ++j)
            cp16(d + dsto[j], srcp[j] + kt*32, szs[j]);
        cp_commit();
    };

    float4 acc[4][8];
    #pragma unroll
    for (int i = 0; i < 4; ++i)
        #pragma unroll
        for (int j = 0; j < 8; ++j) acc[i][j] = make_float4(0.f,0.f,0.f,0.f);

    int nk = K / 32;
    stage(0, 0);
    stage(1, 1);

    const uint32_t* Hs = (const uint32_t*)hsm;   // uint32 (half2) view

    for (int kt = 0; kt < nk; ++kt) {
        cp_wait1();
        __syncthreads();

        int buf = kt % STAGES;
        const uint32_t* as = Hs + buf*STAGE_U32;   // A rows 0..255
        const uint32_t* bs = as + 256*16;          // B rows at row 256

        // fragment loads: row pitch = 32 halves = 16 uint32
        uint4 alo[4], ahi[4], bf[8];
        #pragma unroll
        for (int mf = 0; mf < 4; ++mf) {
            alo[mf] = *(const uint4*)&as[(wm + mf*16 + gid    )*16 + tig*4];
            ahi[mf] = *(const uint4*)&as[(wm + mf*16 + gid + 8)*16 + tig*4];
        }
        #pragma unroll
        for (int nf = 0; nf < 8; ++nf)
            bf[nf] = *(const uint4*)&bs[(wn + nf*8 + gid)*16 + tig*4];

        #pragma unroll
        for (int mf = 0; mf < 4; ++mf)
            #pragma unroll
            for (int nf = 0; nf < 8; ++nf) {
                mma_f16(acc[mf][nf], alo[mf].x, ahi[mf].x, alo[mf].y, ahi[mf].y,
                                     bf[nf].x, bf[nf].y);
                mma_f16(acc[mf][nf], alo[mf].z, ahi[mf].z, alo[mf].w, ahi[mf].w,
                                     bf[nf].z, bf[nf].w);
            }

        int kn = kt + (STAGES - 1);
        if (kn < nk) stage(kn, kn % STAGES);
        else cp_commit();
    }

    // epilogue: (c.x,c.y) -> (row gid, col 2t,2t+1); (c.z,c.w) -> row gid+8
    #pragma unroll
    for (int mf = 0; mf < 4; ++mf) {
        int row = bm*256 + wm + mf*16 + gid;
        #pragma unroll
        for (int nf = 0; nf < 8; ++nf) {
            int col = bn*128 + wn + nf*8 + tig*2;
            if (col < Nn) {
                float4 v = acc[mf][nf];
                if (ACT && col < act_cols) {
                    v.x = 1.f/(1.f + __expf(-(v.x + bias[col])));
                    v.y = 1.f/(1.f + __expf(-(v.y + bias[col+1])));
                    v.z = 1.f/(1.f + __expf(-(v.z + bias[col])));
                    v.w = 1.f/(1.f + __expf(-(v.w + bias[col+1])));
                }
                *(float2*)(C + (size_t)row*Nn + col)     = make_float2(v.x, v.y);
                *(float2*)(C + (size_t)(row+8)*Nn + col) = make_float2(v.z, v.w);
            }
        }
    }
}

// ============================================================
// fused weight pack + fp16 convert
// ============================================================
__global__ void pack_weights(const float4* __restrict__ wG,
                             const float4* __restrict__ wK,
                             const float4* __restrict__ wV,
                             const float4* __restrict__ wQ)
{
    int i = blockIdx.x*blockDim.x + threadIdx.x;   // float4 index
    if (i >= PC*Dd/4) return;
    int row = i / (Dd/4);
    int c4  = i - row*(Dd/4);
    float4 v;
    if (row < 32)        v = wG[row*(Dd/4) + c4];
    else if (row < 544)  v = wK[(row-32)*(Dd/4) + c4];
    else if (row < 1056) v = wV[(row-544)*(Dd/4) + c4];
    else                 v = wQ[(row-1056)*(Dd/4) + c4];
    __half2* o = (__half2*)(g_Wh + (size_t)i*4);
    o[0] = __floats2half2_rn(v.x, v.y);
    o[1] = __floats2half2_rn(v.z, v.w);
}

__global__ void cvt_x(const float4* __restrict__ X, int n4)
{
    int i = blockIdx.x*blockDim.x + threadIdx.x;
    if (i < n4) {
        float4 v = X[i];
        __half2* o = (__half2*)(g_Xh + (size_t)i*4);
        o[0] = __floats2half2_rn(v.x, v.y);
        o[1] = __floats2half2_rn(v.z, v.w);
    }
}

// ============================================================
// Gate combine
// ============================================================
__global__ __launch_bounds__(256) void gate_combine()
{
    int row = blockIdx.x;
    int n = row / T, t = row - n*T;
    __shared__ float sG[H*E];
    int tid = threadIdx.x;
    const float* Pr = g_P + (size_t)row*PC;
    if (tid < H*E) sG[tid] = Pr[tid];
    __syncthreads();
    if (tid < E) {
        float s = 0.f;
        #pragma unroll
        for (int h = 0; h < H; ++h) s += sG[h*E + tid];
        g_A[(n*E + tid)*T + t] = 1.f - fminf(s, 1.f);
    }
    int e = tid >> 6, d = tid & 63;
    float sk = 0.f, sv = 0.f;
    #pragma unroll
    for (int h = 0; h < H; ++h) {
        float g = sG[h*E + e];
        sk = fmaf(g, Pr[32  + h*64 + d], sk);
        sv = fmaf(g, Pr[544 + h*64 + d], sv);
    }
    size_t o = ((size_t)(n*E + e)*T + t)*DK + d;
    g_gK[o] = sk;
    g_gV[o] = sv;
}

// ============================================================
// Scan (pipelined)
// ============================================================
__global__ __launch_bounds__(128) void scan_kernel(
    const float* __restrict__ initK, const float* __restrict__ initV)
{
    __shared__ float sa[TC];
    int b = blockIdx.x;
    int l = b % Lw, e = (b / Lw) % E, n = b / (Lw*E);
    int tid = threadIdx.x;
    bool isV = tid >= 64;
    int d = tid & 63;
    const float* init = isV ? initV : initK;
    const float* g    = isV ? g_gV  : g_gK;
    float*       rec  = isV ? g_recV : g_recK;

    size_t base = (size_t)(n*E + e);
    int t0 = l*TC;
    const float* Arow = g_A + base*T + t0;
    if (tid < TC) sa[tid] = Arow[tid];
    __syncthreads();

    float st = init[(e*Lw + l)*DK + d];
    rec[(base*RLEN + l)*DK + d] = st;
    const float* grow   = g   + (base*T   + t0)*(size_t)DK + d;
    float*       recrow = rec + (base*RLEN + Lw + t0)*(size_t)DK + d;

    float gbuf[8];
    #pragma unroll
    for (int j = 0; j < 8; ++j) gbuf[j] = grow[(size_t)j*DK];

    for (int c0 = 0; c0 < TC; c0 += 8) {
        float gn[8];
        if (c0 + 8 < TC) {
            #pragma unroll
            for (int j = 0; j < 8; ++j) gn[j] = grow[(size_t)(c0+8+j)*DK];
        }
        #pragma unroll
        for (int j = 0; j < 8; ++j) {
            st = fmaf(sa[c0+j], st, gbuf[j]);
            recrow[(size_t)(c0+j)*DK] = st;
        }
        #pragma unroll
        for (int j = 0; j < 8; ++j) gbuf[j] = gn[j];
    }
}

// ============================================================
// Attention: online softmax; writes Y directly as fp16
// ============================================================
extern __shared__ float sm_att[];

__global__ __launch_bounds__(256, 1) void attention_kernel()
{
    float* Ks = sm_att;
    float* Vs = sm_att + WW*SST;
    int bid = blockIdx.x;
    int n    = bid / (T/TQ);
    int tile = bid % (T/TQ);
    int t0 = tile*TQ;
    int tid = threadIdx.x;

    for (int i = tid; i < WW*E*16; i += 256) {
        int w   = i >> 6;
        int rem = i & 63;
        int e = rem >> 4, d4 = rem & 15;
        size_t go = (((size_t)(n*E + e))*RLEN + (1 + t0 + w))*DK + d4*4;
        float4 kv = *(const float4*)(g_recK + go);
        float4 vv = *(const float4*)(g_recV + go);
        int so = w*SST + e*64 + d4*4;
        *(float4*)(Ks + so) = kv;
        *(float4*)(Vs + so) = vv;
    }
    __syncthreads();

    int h = tid & 7, tq = tid >> 3;
    int t = t0 + tq;
    float4 q[16];
    const float* Qp = g_P + (size_t)(n*T + t)*PC + 1056 + h*64;
    #pragma unroll
    for (int i = 0; i < 16; ++i) q[i] = *(const float4*)(Qp + i*4);

    float m = -1e30f, sum = 0.f;
    float4 acc[16];
    #pragma unroll
    for (int i = 0; i < 16; ++i) acc[i] = make_float4(0.f,0.f,0.f,0.f);

    for (int e = 0; e < E; ++e) {
        for (int l = 0; l < Lw; ++l) {
            const float* kp = Ks + (tq + l)*SST + e*64;
            float s = 0.f;
            #pragma unroll
            for (int i = 0; i < 16; ++i) {
                float4 k4 = *(const float4*)(kp + i*4);
                s = fmaf(q[i].x,k4.x, fmaf(q[i].y,k4.y,
                    fmaf(q[i].z,k4.z, fmaf(q[i].w,k4.w, s))));
            }
            s *= 0.125f;
            if (s > m) {
                float f = __expf(m - s);
                sum *= f;
                #pragma unroll
                for (int i = 0; i < 16; ++i) {
                    acc[i].x *= f; acc[i].y *= f; acc[i].z *= f; acc[i].w *= f;
                }
                m = s;
            }
            float p = __expf(s - m);
            sum += p;
            const float* vp = Vs + (tq + l)*SST + e*64;
            #pragma unroll
            for (int i = 0; i < 16; ++i) {
                float4 v4 = *(const float4*)(vp + i*4);
                acc[i].x = fmaf(p, v4.x, acc[i].x);
                acc[i].y = fmaf(p, v4.y, acc[i].y);
                acc[i].z = fmaf(p, v4.z, acc[i].z);
                acc[i].w = fmaf(p, v4.w, acc[i].w);
            }
        }
    }

    float inv = 1.f / sum;
    __half2* Yp = (__half2*)(g_Yh + (size_t)(n*T + t)*(H*DK) + h*64);
    #pragma unroll
    for (int i = 0; i < 16; ++i) {
        Yp[i*2]   = __floats2half2_rn(acc[i].x*inv, acc[i].y*inv);
        Yp[i*2+1] = __floats2half2_rn(acc[i].z*inv, acc[i].w*inv);
    }
}

// ============================================================
// w_O transpose: (512,1024) -> (1024,512), fp16 output
// ============================================================
__global__ void transpose_wo(const float* __restrict__ src)
{
    __shared__ float tile[32][33];
    int tx = threadIdx.x, ty = threadIdx.y;
    int x = blockIdx.x*32 + tx;
    int y = blockIdx.y*32 + ty;
    #pragma unroll
    for (int i = 0; i < 32; i += 8)
        tile[ty+i][tx] = src[(size_t)(y+i)*Dd + x];
    __syncthreads();
    int x2 = blockIdx.y*32 + tx;
    int y2 = blockIdx.x*32 + ty;
    #pragma unroll
    for (int i = 0; i < 32; i += 8)
        g_WoTh[(size_t)(y2+i)*(H*DK) + x2] = __float2half_rn(tile[tx][ty+i]);
}

// ============================================================
extern "C" void kernel_launch(void* const* d_in, const int* in_sizes, int n_in,
                              void* d_out, int out_size)
{
    const float* X  = (const float*)d_in[0];
    const float* wG = (const float*)d_in[1];
    const float* bG = (const float*)d_in[2];
    const float* wK = (const float*)d_in[3];
    const float* wV = (const float*)d_in[4];
    const float* wQ = (const float*)d_in[5];
    const float* wO = (const float*)d_in[6];
    const float* iK = (const float*)d_in[7];
    const float* iV = (const float*)d_in[8];
    float* out = (float*)d_out;

    cudaMemcpyToSymbolAsync(g_bias, bG, 32*sizeof(float), 0, cudaMemcpyDeviceToDevice, 0);

    float *dBias, *dP;
    __half *dXh, *dWh, *dYh, *dWoTh;
    cudaGetSymbolAddress((void**)&dWh,   g_Wh);
    cudaGetSymbolAddress((void**)&dBias, g_bias);
    cudaGetSymbolAddress((void**)&dP,    g_P);
    cudaGetSymbolAddress((void**)&dYh,   g_Yh);
    cudaGetSymbolAddress((void**)&dWoTh, g_WoTh);
    cudaGetSymbolAddress((void**)&dXh,   g_Xh);

    // pack + convert operands to fp16
    pack_weights<<<(PC*Dd/4 + 255)/256, 256>>>(
        (const float4*)wG, (const float4*)wK, (const float4*)wV, (const float4*)wQ);
    cvt_x<<<((NT*Dd/4) + 255)/256, 256>>>((const float4*)X, NT*Dd/4);
    transpose_wo<<<dim3(Dd/32, (H*DK)/32), dim3(32,8)>>>(wO);

    int gsmem = STAGES*STAGE_BYTES;   // 73728 B
    cudaFuncSetAttribute(mgemm<true>,  cudaFuncAttributeMaxDynamicSharedMemorySize, gsmem);
    cudaFuncSetAttribute(mgemm<false>, cudaFuncAttributeMaxDynamicSharedMemorySize, gsmem);

    // 1) fused projection GEMM (fp16 tensor cores, fp32 accum)
    mgemm<true><<<dim3((PC+127)/128, NT/256), 256, gsmem>>>(
        dXh, dWh, dP, NT, PC, Dd, dBias, 32);

    // 2) gates
    gate_combine<<<NT, 256>>>();

    // 3) scans
    scan_kernel<<<Nb*E*Lw, 128>>>(iK, iV);

    // 4) attention
    int smem_bytes = 2*WW*SST*sizeof(float);
    cudaFuncSetAttribute(attention_kernel, cudaFuncAttributeMaxDynamicSharedMemorySize, smem_bytes);
    attention_kernel<<<Nb*(T/TQ), 256, smem_bytes>>>();

    // 5) output projection
    mgemm<false><<<dim3(Dd/128, NT/256), 256, gsmem>>>(
        dYh, dWoTh, out, NT, Dd, H*DK, nullptr, 0);
}

// round 10
// speedup vs baseline: 1.3892x; 1.0767x over previous
#include <cuda_runtime.h>
#include <cuda_fp16.h>
#include <math.h>
#include <stdint.h>

// ---- problem constants ----
#define Nb   2
#define T    4096
#define Dd   1024
#define H    8
#define E    4
#define Lw   32
#define TC   128
#define DK   64
#define NT   (Nb*T)       // 8192
#define PC   1568         // 32 G + 512 K + 512 V + 512 Q
#define RLEN (Lw + T)     // 4128

#define TQ   32
#define WW   63
#define SST  260

#define STAGES 4
// one pipeline stage = 384 rows (256 A + 128 B) x 32 halves (64 B) = 24576 B
#define STAGE_BYTES 24576
#define STAGE_U32   6144

// ---- device scratch ----
__device__ __half  g_Wh[(size_t)PC*Dd];     // fp16 weights (concat)
__device__ float   g_bias[PC];
__device__ __half  g_Xh[(size_t)NT*Dd];     // fp16 X
__device__ float   g_P[(size_t)NT*PC];
__device__ float   g_A[Nb*E*T];
__device__ float   g_gK[(size_t)Nb*E*T*DK];
__device__ float   g_gV[(size_t)Nb*E*T*DK];
__device__ float   g_recK[(size_t)Nb*E*RLEN*DK];
__device__ float   g_recV[(size_t)Nb*E*RLEN*DK];
__device__ __half  g_Yh[(size_t)NT*H*DK];   // fp16 attention output
__device__ __half  g_WoTh[(size_t)Dd*H*DK]; // fp16 w_O^T

// ============================================================
// helpers
// ============================================================
__device__ __forceinline__ void mma_f16(float4& c,
    uint32_t a0, uint32_t a1, uint32_t a2, uint32_t a3,
    uint32_t b0, uint32_t b1)
{
    asm volatile("mma.sync.aligned.m16n8k16.row.col.f32.f16.f16.f32 "
        "{%0,%1,%2,%3}, {%4,%5,%6,%7}, {%8,%9}, {%0,%1,%2,%3};"
        : "+f"(c.x), "+f"(c.y), "+f"(c.z), "+f"(c.w)
        : "r"(a0), "r"(a1), "r"(a2), "r"(a3), "r"(b0), "r"(b1));
}

__device__ __forceinline__ void cp16(uint32_t dst, const void* src, int sz) {
    asm volatile("cp.async.cg.shared.global [%0], [%1], 16, %2;"
                 :: "r"(dst), "l"(src), "r"(sz));
}
__device__ __forceinline__ void cp_commit() { asm volatile("cp.async.commit_group;"); }
__device__ __forceinline__ void cp_wait2()  { asm volatile("cp.async.wait_group 2;"); }

// packed fp32x2 math (sm_100+ base ISA) — exact fp32 semantics, 2 lanes/op
__device__ __forceinline__ uint64_t pack2(float lo, float hi) {
    uint64_t r;
    asm("mov.b64 %0, {%1, %2};" : "=l"(r)
        : "r"(__float_as_uint(lo)), "r"(__float_as_uint(hi)));
    return r;
}
__device__ __forceinline__ void unpack2(uint64_t v, float& lo, float& hi) {
    uint32_t a, b;
    asm("mov.b64 {%0, %1}, %2;" : "=r"(a), "=r"(b) : "l"(v));
    lo = __uint_as_float(a); hi = __uint_as_float(b);
}
__device__ __forceinline__ uint64_t ffma2(uint64_t a, uint64_t b, uint64_t c) {
    uint64_t d;
    asm("fma.rn.f32x2 %0, %1, %2, %3;" : "=l"(d) : "l"(a), "l"(b), "l"(c));
    return d;
}
__device__ __forceinline__ uint64_t fmul2(uint64_t a, uint64_t b) {
    uint64_t d;
    asm("mul.rn.f32x2 %0, %1, %2;" : "=l"(d) : "l"(a), "l"(b));
    return d;
}

// ============================================================
// FP16 GEMM (NT): C[M][Nn] = A[M][K] * B[Nn][K]^T, fp32 accum.
// BM=256, BN=128, BK=32 per stage. 256 threads, 8 warps of 64x64.
// 4-stage cp.async pipeline, main loop unrolled x4 so the stage
// index is compile-time (LDS with immediate offsets, less ALU);
// wait_group 2 keeps two stages in flight.
// ============================================================
template<bool ACT>
__global__ __launch_bounds__(256, 1) void mgemm(
    const __half* __restrict__ A, const __half* __restrict__ B,
    float* __restrict__ C, int M, int Nn, int K,
    const float* __restrict__ bias, int act_cols)
{
    extern __shared__ __align__(16) __half hsm[];

    int tid  = threadIdx.x;
    int bm   = blockIdx.y, bn = blockIdx.x;
    int warp = tid >> 5, lane = tid & 31;
    int wm   = (warp >> 1) * 64;          // 0,64,128,192
    int wn   = (warp & 1) * 64;           // 0,64
    int gid  = lane >> 2, tig = lane & 3;

    uint32_t sbase = (uint32_t)__cvta_generic_to_shared(hsm);

    // staging: 1536 16B chunks per stage, 6 per thread (precomputed)
    const __half* srcp[6];
    uint32_t dsto[6];
    int szs[6];
    #pragma unroll
    for (int j = 0; j < 6; ++j) {
        int i = j*256 + tid;              // chunk index 0..1535
        int row = i >> 2, c = i & 3;      // 4 chunks (64 B) per row
        bool isA = row < 256;
        int g  = isA ? (bm*256 + row) : (bn*128 + (row - 256));
        int sz = isA ? 16 : ((g < Nn) ? 16 : 0);
        srcp[j] = (isA ? A + (size_t)g*K
                       : B + (size_t)(sz ? g : 0)*K) + c*8;
        dsto[j] = row*64 + c*16;
        szs[j]  = sz;
    }

    auto stage = [&](int kt, int s) {
        uint32_t d = sbase + s*STAGE_BYTES;
        #pragma unroll
        for (int j = 0; j < 6; ++j)
            cp16(d + dsto[j], srcp[j] + kt*32, szs[j]);
        cp_commit();
    };

    float4 acc[4][8];
    #pragma unroll
    for (int i = 0; i < 4; ++i)
        #pragma unroll
        for (int j = 0; j < 8; ++j) acc[i][j] = make_float4(0.f,0.f,0.f,0.f);

    int nk = K / 32;                      // 32 or 16: divisible by 4
    stage(0, 0);
    stage(1, 1);
    stage(2, 2);

    const uint32_t* Hs = (const uint32_t*)hsm;   // uint32 (half2) view

    for (int kt0 = 0; kt0 < nk; kt0 += 4) {
        #pragma unroll
        for (int u = 0; u < 4; ++u) {
            int kt = kt0 + u;
            cp_wait2();
            __syncthreads();

            const uint32_t* as = Hs + u*STAGE_U32;   // compile-time stage
            const uint32_t* bs = as + 256*16;        // B rows at row 256

            uint4 alo[4], ahi[4], bf[8];
            #pragma unroll
            for (int mf = 0; mf < 4; ++mf) {
                alo[mf] = *(const uint4*)&as[(wm + mf*16 + gid    )*16 + tig*4];
                ahi[mf] = *(const uint4*)&as[(wm + mf*16 + gid + 8)*16 + tig*4];
            }
            #pragma unroll
            for (int nf = 0; nf < 8; ++nf)
                bf[nf] = *(const uint4*)&bs[(wn + nf*8 + gid)*16 + tig*4];

            #pragma unroll
            for (int mf = 0; mf < 4; ++mf)
                #pragma unroll
                for (int nf = 0; nf < 8; ++nf) {
                    mma_f16(acc[mf][nf], alo[mf].x, ahi[mf].x, alo[mf].y, ahi[mf].y,
                                         bf[nf].x, bf[nf].y);
                    mma_f16(acc[mf][nf], alo[mf].z, ahi[mf].z, alo[mf].w, ahi[mf].w,
                                         bf[nf].z, bf[nf].w);
                }

            int kn = kt + 3;
            if (kn < nk) stage(kn, (u + 3) & 3);
            else cp_commit();             // empty group keeps wait window honest
        }
    }

    // epilogue
    #pragma unroll
    for (int mf = 0; mf < 4; ++mf) {
        int row = bm*256 + wm + mf*16 + gid;
        #pragma unroll
        for (int nf = 0; nf < 8; ++nf) {
            int col = bn*128 + wn + nf*8 + tig*2;
            if (col < Nn) {
                float4 v = acc[mf][nf];
                if (ACT && col < act_cols) {
                    v.x = 1.f/(1.f + __expf(-(v.x + bias[col])));
                    v.y = 1.f/(1.f + __expf(-(v.y + bias[col+1])));
                    v.z = 1.f/(1.f + __expf(-(v.z + bias[col])));
                    v.w = 1.f/(1.f + __expf(-(v.w + bias[col+1])));
                }
                *(float2*)(C + (size_t)row*Nn + col)     = make_float2(v.x, v.y);
                *(float2*)(C + (size_t)(row+8)*Nn + col) = make_float2(v.z, v.w);
            }
        }
    }
}

// ============================================================
// fused weight pack + fp16 convert
// ============================================================
__global__ void pack_weights(const float4* __restrict__ wG,
                             const float4* __restrict__ wK,
                             const float4* __restrict__ wV,
                             const float4* __restrict__ wQ)
{
    int i = blockIdx.x*blockDim.x + threadIdx.x;
    if (i >= PC*Dd/4) return;
    int row = i / (Dd/4);
    int c4  = i - row*(Dd/4);
    float4 v;
    if (row < 32)        v = wG[row*(Dd/4) + c4];
    else if (row < 544)  v = wK[(row-32)*(Dd/4) + c4];
    else if (row < 1056) v = wV[(row-544)*(Dd/4) + c4];
    else                 v = wQ[(row-1056)*(Dd/4) + c4];
    __half2* o = (__half2*)(g_Wh + (size_t)i*4);
    o[0] = __floats2half2_rn(v.x, v.y);
    o[1] = __floats2half2_rn(v.z, v.w);
}

__global__ void cvt_x(const float4* __restrict__ X, int n4)
{
    int i = blockIdx.x*blockDim.x + threadIdx.x;
    if (i < n4) {
        float4 v = X[i];
        __half2* o = (__half2*)(g_Xh + (size_t)i*4);
        o[0] = __floats2half2_rn(v.x, v.y);
        o[1] = __floats2half2_rn(v.z, v.w);
    }
}

// ============================================================
// Gate combine
// ============================================================
__global__ __launch_bounds__(256) void gate_combine()
{
    int row = blockIdx.x;
    int n = row / T, t = row - n*T;
    __shared__ float sG[H*E];
    int tid = threadIdx.x;
    const float* Pr = g_P + (size_t)row*PC;
    if (tid < H*E) sG[tid] = Pr[tid];
    __syncthreads();
    if (tid < E) {
        float s = 0.f;
        #pragma unroll
        for (int h = 0; h < H; ++h) s += sG[h*E + tid];
        g_A[(n*E + tid)*T + t] = 1.f - fminf(s, 1.f);
    }
    int e = tid >> 6, d = tid & 63;
    float sk = 0.f, sv = 0.f;
    #pragma unroll
    for (int h = 0; h < H; ++h) {
        float g = sG[h*E + e];
        sk = fmaf(g, Pr[32  + h*64 + d], sk);
        sv = fmaf(g, Pr[544 + h*64 + d], sv);
    }
    size_t o = ((size_t)(n*E + e)*T + t)*DK + d;
    g_gK[o] = sk;
    g_gV[o] = sv;
}

// ============================================================
// Scan (pipelined)
// ============================================================
__global__ __launch_bounds__(128) void scan_kernel(
    const float* __restrict__ initK, const float* __restrict__ initV)
{
    __shared__ float sa[TC];
    int b = blockIdx.x;
    int l = b % Lw, e = (b / Lw) % E, n = b / (Lw*E);
    int tid = threadIdx.x;
    bool isV = tid >= 64;
    int d = tid & 63;
    const float* init = isV ? initV : initK;
    const float* g    = isV ? g_gV  : g_gK;
    float*       rec  = isV ? g_recV : g_recK;

    size_t base = (size_t)(n*E + e);
    int t0 = l*TC;
    const float* Arow = g_A + base*T + t0;
    if (tid < TC) sa[tid] = Arow[tid];
    __syncthreads();

    float st = init[(e*Lw + l)*DK + d];
    rec[(base*RLEN + l)*DK + d] = st;
    const float* grow   = g   + (base*T   + t0)*(size_t)DK + d;
    float*       recrow = rec + (base*RLEN + Lw + t0)*(size_t)DK + d;

    float gbuf[8];
    #pragma unroll
    for (int j = 0; j < 8; ++j) gbuf[j] = grow[(size_t)j*DK];

    for (int c0 = 0; c0 < TC; c0 += 8) {
        float gn[8];
        if (c0 + 8 < TC) {
            #pragma unroll
            for (int j = 0; j < 8; ++j) gn[j] = grow[(size_t)(c0+8+j)*DK];
        }
        #pragma unroll
        for (int j = 0; j < 8; ++j) {
            st = fmaf(sa[c0+j], st, gbuf[j]);
            recrow[(size_t)(c0+j)*DK] = st;
        }
        #pragma unroll
        for (int j = 0; j < 8; ++j) gbuf[j] = gn[j];
    }
}

// ============================================================
// Attention: online softmax with packed fp32x2 FMA (exact fp32).
// Per position: 32 FFMA2 (scores, 2 chains) + 32 FFMA2 (V accum)
// instead of 128 scalar FFMA. Writes Y directly as fp16.
// ============================================================
extern __shared__ float sm_att[];

__global__ __launch_bounds__(256, 1) void attention_kernel()
{
    float* Ks = sm_att;
    float* Vs = sm_att + WW*SST;
    int bid = blockIdx.x;
    int n    = bid / (T/TQ);
    int tile = bid % (T/TQ);
    int t0 = tile*TQ;
    int tid = threadIdx.x;

    for (int i = tid; i < WW*E*16; i += 256) {
        int w   = i >> 6;
        int rem = i & 63;
        int e = rem >> 4, d4 = rem & 15;
        size_t go = (((size_t)(n*E + e))*RLEN + (1 + t0 + w))*DK + d4*4;
        float4 kv = *(const float4*)(g_recK + go);
        float4 vv = *(const float4*)(g_recV + go);
        int so = w*SST + e*64 + d4*4;
        *(float4*)(Ks + so) = kv;
        *(float4*)(Vs + so) = vv;
    }
    __syncthreads();

    int h = tid & 7, tq = tid >> 3;
    int t = t0 + tq;

    // Q as 32 packed f32x2 (dims 2j, 2j+1)
    uint64_t q2[32];
    const ulonglong2* Qp2 = (const ulonglong2*)(g_P + (size_t)(n*T + t)*PC + 1056 + h*64);
    #pragma unroll
    for (int i = 0; i < 16; ++i) {
        ulonglong2 v = Qp2[i];
        q2[2*i]   = v.x;
        q2[2*i+1] = v.y;
    }

    float m = -1e30f, sum = 0.f;
    uint64_t acc2[32];
    #pragma unroll
    for (int i = 0; i < 32; ++i) acc2[i] = 0ull;

    for (int e = 0; e < E; ++e) {
        for (int l = 0; l < Lw; ++l) {
            int base = (tq + l)*SST + e*64;
            const ulonglong2* kp2 = (const ulonglong2*)(Ks + base);
            uint64_t sa = 0ull, sb = 0ull;
            #pragma unroll
            for (int i = 0; i < 8; ++i) {
                ulonglong2 k0 = kp2[2*i];
                ulonglong2 k1 = kp2[2*i+1];
                sa = ffma2(q2[4*i],   k0.x, sa);
                sb = ffma2(q2[4*i+1], k0.y, sb);
                sa = ffma2(q2[4*i+2], k1.x, sa);
                sb = ffma2(q2[4*i+3], k1.y, sb);
            }
            float a0, a1, b0, b1;
            unpack2(sa, a0, a1);
            unpack2(sb, b0, b1);
            float s = ((a0 + a1) + (b0 + b1)) * 0.125f;

            if (s > m) {
                float f = __expf(m - s);
                sum *= f;
                uint64_t f2 = pack2(f, f);
                #pragma unroll
                for (int i = 0; i < 32; ++i) acc2[i] = fmul2(acc2[i], f2);
                m = s;
            }
            float p = __expf(s - m);
            sum += p;
            uint64_t p2 = pack2(p, p);
            const ulonglong2* vp2 = (const ulonglong2*)(Vs + base);
            #pragma unroll
            for (int i = 0; i < 16; ++i) {
                ulonglong2 v = vp2[i];
                acc2[2*i]   = ffma2(p2, v.x, acc2[2*i]);
                acc2[2*i+1] = ffma2(p2, v.y, acc2[2*i+1]);
            }
        }
    }

    float inv = 1.f / sum;
    __half2* Yp = (__half2*)(g_Yh + (size_t)(n*T + t)*(H*DK) + h*64);
    #pragma unroll
    for (int i = 0; i < 32; ++i) {
        float lo, hi;
        unpack2(acc2[i], lo, hi);
        Yp[i] = __floats2half2_rn(lo*inv, hi*inv);
    }
}

// ============================================================
// w_O transpose: (512,1024) -> (1024,512), fp16 output
// ============================================================
__global__ void transpose_wo(const float* __restrict__ src)
{
    __shared__ float tile[32][33];
    int tx = threadIdx.x, ty = threadIdx.y;
    int x = blockIdx.x*32 + tx;
    int y = blockIdx.y*32 + ty;
    #pragma unroll
    for (int i = 0; i < 32; i += 8)
        tile[ty+i][tx] = src[(size_t)(y+i)*Dd + x];
    __syncthreads();
    int x2 = blockIdx.y*32 + tx;
    int y2 = blockIdx.x*32 + ty;
    #pragma unroll
    for (int i = 0; i < 32; i += 8)
        g_WoTh[(size_t)(y2+i)*(H*DK) + x2] = __float2half_rn(tile[tx][ty+i]);
}

// ============================================================
extern "C" void kernel_launch(void* const* d_in, const int* in_sizes, int n_in,
                              void* d_out, int out_size)
{
    const float* X  = (const float*)d_in[0];
    const float* wG = (const float*)d_in[1];
    const float* bG = (const float*)d_in[2];
    const float* wK = (const float*)d_in[3];
    const float* wV = (const float*)d_in[4];
    const float* wQ = (const float*)d_in[5];
    const float* wO = (const float*)d_in[6];
    const float* iK = (const float*)d_in[7];
    const float* iV = (const float*)d_in[8];
    float* out = (float*)d_out;

    cudaMemcpyToSymbolAsync(g_bias, bG, 32*sizeof(float), 0, cudaMemcpyDeviceToDevice, 0);

    float *dBias, *dP;
    __half *dXh, *dWh, *dYh, *dWoTh;
    cudaGetSymbolAddress((void**)&dWh,   g_Wh);
    cudaGetSymbolAddress((void**)&dBias, g_bias);
    cudaGetSymbolAddress((void**)&dP,    g_P);
    cudaGetSymbolAddress((void**)&dYh,   g_Yh);
    cudaGetSymbolAddress((void**)&dWoTh, g_WoTh);
    cudaGetSymbolAddress((void**)&dXh,   g_Xh);

    // pack + convert operands to fp16
    pack_weights<<<(PC*Dd/4 + 255)/256, 256>>>(
        (const float4*)wG, (const float4*)wK, (const float4*)wV, (const float4*)wQ);
    cvt_x<<<((NT*Dd/4) + 255)/256, 256>>>((const float4*)X, NT*Dd/4);
    transpose_wo<<<dim3(Dd/32, (H*DK)/32), dim3(32,8)>>>(wO);

    int gsmem = STAGES*STAGE_BYTES;   // 98304 B
    cudaFuncSetAttribute(mgemm<true>,  cudaFuncAttributeMaxDynamicSharedMemorySize, gsmem);
    cudaFuncSetAttribute(mgemm<false>, cudaFuncAttributeMaxDynamicSharedMemorySize, gsmem);

    // 1) fused projection GEMM (fp16 tensor cores, fp32 accum)
    mgemm<true><<<dim3((PC+127)/128, NT/256), 256, gsmem>>>(
        dXh, dWh, dP, NT, PC, Dd, dBias, 32);

    // 2) gates
    gate_combine<<<NT, 256>>>();

    // 3) scans
    scan_kernel<<<Nb*E*Lw, 128>>>(iK, iV);

    // 4) attention (packed f32x2)
    int smem_bytes = 2*WW*SST*sizeof(float);
    cudaFuncSetAttribute(attention_kernel, cudaFuncAttributeMaxDynamicSharedMemorySize, smem_bytes);
    attention_kernel<<<Nb*(T/TQ), 256, smem_bytes>>>();

    // 5) output projection
    mgemm<false><<<dim3(Dd/128, NT/256), 256, gsmem>>>(
        dYh, dWoTh, out, NT, Dd, H*DK, nullptr, 0);
}

// round 11
// speedup vs baseline: 1.4430x; 1.0387x over previous
#include <cuda_runtime.h>
#include <cuda_fp16.h>
#include <math.h>
#include <stdint.h>

// ---- problem constants ----
#define Nb   2
#define T    4096
#define Dd   1024
#define H    8
#define E    4
#define Lw   32
#define TC   128
#define DK   64
#define NT   (Nb*T)       // 8192
#define PC   1568         // 32 G + 512 K + 512 V + 512 Q
#define RLEN (Lw + T)     // 4128

#define TQ   32
#define WW   63
#define SST  260

#define STAGES 4
// one pipeline stage = 256 rows (128 A + 128 B) x 32 halves (64 B) = 16384 B
#define STAGE_BYTES 16384
#define STAGE_U32   4096

// ---- device scratch ----
__device__ __half  g_Wh[(size_t)PC*Dd];     // fp16 weights (concat)
__device__ float   g_bias[PC];
__device__ __half  g_Xh[(size_t)NT*Dd];     // fp16 X
__device__ float   g_P[(size_t)NT*PC];
__device__ float   g_A[Nb*E*T];
__device__ float   g_gK[(size_t)Nb*E*T*DK];
__device__ float   g_gV[(size_t)Nb*E*T*DK];
__device__ float   g_recK[(size_t)Nb*E*RLEN*DK];
__device__ float   g_recV[(size_t)Nb*E*RLEN*DK];
__device__ __half  g_Yh[(size_t)NT*H*DK];   // fp16 attention output
__device__ __half  g_WoTh[(size_t)Dd*H*DK]; // fp16 w_O^T

// ============================================================
// helpers
// ============================================================
__device__ __forceinline__ void mma_f16(float4& c,
    uint32_t a0, uint32_t a1, uint32_t a2, uint32_t a3,
    uint32_t b0, uint32_t b1)
{
    asm volatile("mma.sync.aligned.m16n8k16.row.col.f32.f16.f16.f32 "
        "{%0,%1,%2,%3}, {%4,%5,%6,%7}, {%8,%9}, {%0,%1,%2,%3};"
        : "+f"(c.x), "+f"(c.y), "+f"(c.z), "+f"(c.w)
        : "r"(a0), "r"(a1), "r"(a2), "r"(a3), "r"(b0), "r"(b1));
}

__device__ __forceinline__ void cp16(uint32_t dst, const void* src, int sz) {
    asm volatile("cp.async.cg.shared.global [%0], [%1], 16, %2;"
                 :: "r"(dst), "l"(src), "r"(sz));
}
__device__ __forceinline__ void cp_commit() { asm volatile("cp.async.commit_group;"); }
__device__ __forceinline__ void cp_wait2()  { asm volatile("cp.async.wait_group 2;"); }

// packed fp32x2 math (sm_100+ base ISA) — exact fp32 semantics, 2 lanes/op
__device__ __forceinline__ uint64_t pack2(float lo, float hi) {
    uint64_t r;
    asm("mov.b64 %0, {%1, %2};" : "=l"(r)
        : "r"(__float_as_uint(lo)), "r"(__float_as_uint(hi)));
    return r;
}
__device__ __forceinline__ void unpack2(uint64_t v, float& lo, float& hi) {
    uint32_t a, b;
    asm("mov.b64 {%0, %1}, %2;" : "=r"(a), "=r"(b) : "l"(v));
    lo = __uint_as_float(a); hi = __uint_as_float(b);
}
__device__ __forceinline__ uint64_t ffma2(uint64_t a, uint64_t b, uint64_t c) {
    uint64_t d;
    asm("fma.rn.f32x2 %0, %1, %2, %3;" : "=l"(d) : "l"(a), "l"(b), "l"(c));
    return d;
}
__device__ __forceinline__ uint64_t fmul2(uint64_t a, uint64_t b) {
    uint64_t d;
    asm("mul.rn.f32x2 %0, %1, %2;" : "=l"(d) : "l"(a), "l"(b));
    return d;
}

// ============================================================
// FP16 GEMM (NT): C[M][Nn] = A[M][K] * B[Nn][K]^T, fp32 accum.
// BM=128, BN=128, BK=32 per stage. 128 threads, 4 warps of 64x64
// (2x2 warp grid). 4-stage cp.async pipeline (unrolled x4 so stage
// indices are compile-time), wait_group 2, 2 CTAs/SM so barriers
// stall only half the SM and pipelines interleave.
// ============================================================
template<bool ACT>
__global__ __launch_bounds__(128, 2) void mgemm(
    const __half* __restrict__ A, const __half* __restrict__ B,
    float* __restrict__ C, int M, int Nn, int K,
    const float* __restrict__ bias, int act_cols)
{
    extern __shared__ __align__(16) __half hsm[];

    int tid  = threadIdx.x;
    int bm   = blockIdx.y, bn = blockIdx.x;
    int warp = tid >> 5, lane = tid & 31;
    int wm   = (warp >> 1) * 64;          // 0,64
    int wn   = (warp & 1) * 64;           // 0,64
    int gid  = lane >> 2, tig = lane & 3;

    uint32_t sbase = (uint32_t)__cvta_generic_to_shared(hsm);

    // staging: 1024 16B chunks per stage, 8 per thread (precomputed)
    const __half* srcp[8];
    uint32_t dsto[8];
    int szs[8];
    #pragma unroll
    for (int j = 0; j < 8; ++j) {
        int i = j*128 + tid;              // chunk index 0..1023
        int row = i >> 2, c = i & 3;      // 4 chunks (64 B) per row
        bool isA = row < 128;
        int g  = isA ? (bm*128 + row) : (bn*128 + (row - 128));
        int sz = isA ? 16 : ((g < Nn) ? 16 : 0);
        srcp[j] = (isA ? A + (size_t)g*K
                       : B + (size_t)(sz ? g : 0)*K) + c*8;
        dsto[j] = row*64 + c*16;
        szs[j]  = sz;
    }

    auto stage = [&](int kt, int s) {
        uint32_t d = sbase + s*STAGE_BYTES;
        #pragma unroll
        for (int j = 0; j < 8; ++j)
            cp16(d + dsto[j], srcp[j] + kt*32, szs[j]);
        cp_commit();
    };

    float4 acc[4][8];
    #pragma unroll
    for (int i = 0; i < 4; ++i)
        #pragma unroll
        for (int j = 0; j < 8; ++j) acc[i][j] = make_float4(0.f,0.f,0.f,0.f);

    int nk = K / 32;                      // 32 or 16: divisible by 4
    stage(0, 0);
    stage(1, 1);
    stage(2, 2);

    const uint32_t* Hs = (const uint32_t*)hsm;   // uint32 (half2) view

    for (int kt0 = 0; kt0 < nk; kt0 += 4) {
        #pragma unroll
        for (int u = 0; u < 4; ++u) {
            int kt = kt0 + u;
            cp_wait2();
            __syncthreads();

            const uint32_t* as = Hs + u*STAGE_U32;   // compile-time stage
            const uint32_t* bs = as + 128*16;        // B rows at row 128

            uint4 alo[4], ahi[4], bf[8];
            #pragma unroll
            for (int mf = 0; mf < 4; ++mf) {
                alo[mf] = *(const uint4*)&as[(wm + mf*16 + gid    )*16 + tig*4];
                ahi[mf] = *(const uint4*)&as[(wm + mf*16 + gid + 8)*16 + tig*4];
            }
            #pragma unroll
            for (int nf = 0; nf < 8; ++nf)
                bf[nf] = *(const uint4*)&bs[(wn + nf*8 + gid)*16 + tig*4];

            #pragma unroll
            for (int mf = 0; mf < 4; ++mf)
                #pragma unroll
                for (int nf = 0; nf < 8; ++nf) {
                    mma_f16(acc[mf][nf], alo[mf].x, ahi[mf].x, alo[mf].y, ahi[mf].y,
                                         bf[nf].x, bf[nf].y);
                    mma_f16(acc[mf][nf], alo[mf].z, ahi[mf].z, alo[mf].w, ahi[mf].w,
                                         bf[nf].z, bf[nf].w);
                }

            int kn = kt + 3;
            if (kn < nk) stage(kn, (u + 3) & 3);
            else cp_commit();             // empty group keeps wait window honest
        }
    }

    // epilogue
    #pragma unroll
    for (int mf = 0; mf < 4; ++mf) {
        int row = bm*128 + wm + mf*16 + gid;
        #pragma unroll
        for (int nf = 0; nf < 8; ++nf) {
            int col = bn*128 + wn + nf*8 + tig*2;
            if (col < Nn) {
                float4 v = acc[mf][nf];
                if (ACT && col < act_cols) {
                    v.x = 1.f/(1.f + __expf(-(v.x + bias[col])));
                    v.y = 1.f/(1.f + __expf(-(v.y + bias[col+1])));
                    v.z = 1.f/(1.f + __expf(-(v.z + bias[col])));
                    v.w = 1.f/(1.f + __expf(-(v.w + bias[col+1])));
                }
                *(float2*)(C + (size_t)row*Nn + col)     = make_float2(v.x, v.y);
                *(float2*)(C + (size_t)(row+8)*Nn + col) = make_float2(v.z, v.w);
            }
        }
    }
}

// ============================================================
// fused weight pack + fp16 convert
// ============================================================
__global__ void pack_weights(const float4* __restrict__ wG,
                             const float4* __restrict__ wK,
                             const float4* __restrict__ wV,
                             const float4* __restrict__ wQ)
{
    int i = blockIdx.x*blockDim.x + threadIdx.x;
    if (i >= PC*Dd/4) return;
    int row = i / (Dd/4);
    int c4  = i - row*(Dd/4);
    float4 v;
    if (row < 32)        v = wG[row*(Dd/4) + c4];
    else if (row < 544)  v = wK[(row-32)*(Dd/4) + c4];
    else if (row < 1056) v = wV[(row-544)*(Dd/4) + c4];
    else                 v = wQ[(row-1056)*(Dd/4) + c4];
    __half2* o = (__half2*)(g_Wh + (size_t)i*4);
    o[0] = __floats2half2_rn(v.x, v.y);
    o[1] = __floats2half2_rn(v.z, v.w);
}

__global__ void cvt_x(const float4* __restrict__ X, int n4)
{
    int i = blockIdx.x*blockDim.x + threadIdx.x;
    if (i < n4) {
        float4 v = X[i];
        __half2* o = (__half2*)(g_Xh + (size_t)i*4);
        o[0] = __floats2half2_rn(v.x, v.y);
        o[1] = __floats2half2_rn(v.z, v.w);
    }
}

// ============================================================
// Gate combine
// ============================================================
__global__ __launch_bounds__(256) void gate_combine()
{
    int row = blockIdx.x;
    int n = row / T, t = row - n*T;
    __shared__ float sG[H*E];
    int tid = threadIdx.x;
    const float* Pr = g_P + (size_t)row*PC;
    if (tid < H*E) sG[tid] = Pr[tid];
    __syncthreads();
    if (tid < E) {
        float s = 0.f;
        #pragma unroll
        for (int h = 0; h < H; ++h) s += sG[h*E + tid];
        g_A[(n*E + tid)*T + t] = 1.f - fminf(s, 1.f);
    }
    int e = tid >> 6, d = tid & 63;
    float sk = 0.f, sv = 0.f;
    #pragma unroll
    for (int h = 0; h < H; ++h) {
        float g = sG[h*E + e];
        sk = fmaf(g, Pr[32  + h*64 + d], sk);
        sv = fmaf(g, Pr[544 + h*64 + d], sv);
    }
    size_t o = ((size_t)(n*E + e)*T + t)*DK + d;
    g_gK[o] = sk;
    g_gV[o] = sv;
}

// ============================================================
// Scan (pipelined)
// ============================================================
__global__ __launch_bounds__(128) void scan_kernel(
    const float* __restrict__ initK, const float* __restrict__ initV)
{
    __shared__ float sa[TC];
    int b = blockIdx.x;
    int l = b % Lw, e = (b / Lw) % E, n = b / (Lw*E);
    int tid = threadIdx.x;
    bool isV = tid >= 64;
    int d = tid & 63;
    const float* init = isV ? initV : initK;
    const float* g    = isV ? g_gV  : g_gK;
    float*       rec  = isV ? g_recV : g_recK;

    size_t base = (size_t)(n*E + e);
    int t0 = l*TC;
    const float* Arow = g_A + base*T + t0;
    if (tid < TC) sa[tid] = Arow[tid];
    __syncthreads();

    float st = init[(e*Lw + l)*DK + d];
    rec[(base*RLEN + l)*DK + d] = st;
    const float* grow   = g   + (base*T   + t0)*(size_t)DK + d;
    float*       recrow = rec + (base*RLEN + Lw + t0)*(size_t)DK + d;

    float gbuf[8];
    #pragma unroll
    for (int j = 0; j < 8; ++j) gbuf[j] = grow[(size_t)j*DK];

    for (int c0 = 0; c0 < TC; c0 += 8) {
        float gn[8];
        if (c0 + 8 < TC) {
            #pragma unroll
            for (int j = 0; j < 8; ++j) gn[j] = grow[(size_t)(c0+8+j)*DK];
        }
        #pragma unroll
        for (int j = 0; j < 8; ++j) {
            st = fmaf(sa[c0+j], st, gbuf[j]);
            recrow[(size_t)(c0+j)*DK] = st;
        }
        #pragma unroll
        for (int j = 0; j < 8; ++j) gbuf[j] = gn[j];
    }
}

// ============================================================
// Attention: online softmax with packed fp32x2 FMA (exact fp32).
// ============================================================
extern __shared__ float sm_att[];

__global__ __launch_bounds__(256, 1) void attention_kernel()
{
    float* Ks = sm_att;
    float* Vs = sm_att + WW*SST;
    int bid = blockIdx.x;
    int n    = bid / (T/TQ);
    int tile = bid % (T/TQ);
    int t0 = tile*TQ;
    int tid = threadIdx.x;

    for (int i = tid; i < WW*E*16; i += 256) {
        int w   = i >> 6;
        int rem = i & 63;
        int e = rem >> 4, d4 = rem & 15;
        size_t go = (((size_t)(n*E + e))*RLEN + (1 + t0 + w))*DK + d4*4;
        float4 kv = *(const float4*)(g_recK + go);
        float4 vv = *(const float4*)(g_recV + go);
        int so = w*SST + e*64 + d4*4;
        *(float4*)(Ks + so) = kv;
        *(float4*)(Vs + so) = vv;
    }
    __syncthreads();

    int h = tid & 7, tq = tid >> 3;
    int t = t0 + tq;

    // Q as 32 packed f32x2 (dims 2j, 2j+1)
    uint64_t q2[32];
    const ulonglong2* Qp2 = (const ulonglong2*)(g_P + (size_t)(n*T + t)*PC + 1056 + h*64);
    #pragma unroll
    for (int i = 0; i < 16; ++i) {
        ulonglong2 v = Qp2[i];
        q2[2*i]   = v.x;
        q2[2*i+1] = v.y;
    }

    float m = -1e30f, sum = 0.f;
    uint64_t acc2[32];
    #pragma unroll
    for (int i = 0; i < 32; ++i) acc2[i] = 0ull;

    for (int e = 0; e < E; ++e) {
        for (int l = 0; l < Lw; ++l) {
            int base = (tq + l)*SST + e*64;
            const ulonglong2* kp2 = (const ulonglong2*)(Ks + base);
            uint64_t sa = 0ull, sb = 0ull;
            #pragma unroll
            for (int i = 0; i < 8; ++i) {
                ulonglong2 k0 = kp2[2*i];
                ulonglong2 k1 = kp2[2*i+1];
                sa = ffma2(q2[4*i],   k0.x, sa);
                sb = ffma2(q2[4*i+1], k0.y, sb);
                sa = ffma2(q2[4*i+2], k1.x, sa);
                sb = ffma2(q2[4*i+3], k1.y, sb);
            }
            float a0, a1, b0, b1;
            unpack2(sa, a0, a1);
            unpack2(sb, b0, b1);
            float s = ((a0 + a1) + (b0 + b1)) * 0.125f;

            if (s > m) {
                float f = __expf(m - s);
                sum *= f;
                uint64_t f2 = pack2(f, f);
                #pragma unroll
                for (int i = 0; i < 32; ++i) acc2[i] = fmul2(acc2[i], f2);
                m = s;
            }
            float p = __expf(s - m);
            sum += p;
            uint64_t p2 = pack2(p, p);
            const ulonglong2* vp2 = (const ulonglong2*)(Vs + base);
            #pragma unroll
            for (int i = 0; i < 16; ++i) {
                ulonglong2 v = vp2[i];
                acc2[2*i]   = ffma2(p2, v.x, acc2[2*i]);
                acc2[2*i+1] = ffma2(p2, v.y, acc2[2*i+1]);
            }
        }
    }

    float inv = 1.f / sum;
    __half2* Yp = (__half2*)(g_Yh + (size_t)(n*T + t)*(H*DK) + h*64);
    #pragma unroll
    for (int i = 0; i < 32; ++i) {
        float lo, hi;
        unpack2(acc2[i], lo, hi);
        Yp[i] = __floats2half2_rn(lo*inv, hi*inv);
    }
}

// ============================================================
// w_O transpose: (512,1024) -> (1024,512), fp16 output
// ============================================================
__global__ void transpose_wo(const float* __restrict__ src)
{
    __shared__ float tile[32][33];
    int tx = threadIdx.x, ty = threadIdx.y;
    int x = blockIdx.x*32 + tx;
    int y = blockIdx.y*32 + ty;
    #pragma unroll
    for (int i = 0; i < 32; i += 8)
        tile[ty+i][tx] = src[(size_t)(y+i)*Dd + x];
    __syncthreads();
    int x2 = blockIdx.y*32 + tx;
    int y2 = blockIdx.x*32 + ty;
    #pragma unroll
    for (int i = 0; i < 32; i += 8)
        g_WoTh[(size_t)(y2+i)*(H*DK) + x2] = __float2half_rn(tile[tx][ty+i]);
}

// ============================================================
extern "C" void kernel_launch(void* const* d_in, const int* in_sizes, int n_in,
                              void* d_out, int out_size)
{
    const float* X  = (const float*)d_in[0];
    const float* wG = (const float*)d_in[1];
    const float* bG = (const float*)d_in[2];
    const float* wK = (const float*)d_in[3];
    const float* wV = (const float*)d_in[4];
    const float* wQ = (const float*)d_in[5];
    const float* wO = (const float*)d_in[6];
    const float* iK = (const float*)d_in[7];
    const float* iV = (const float*)d_in[8];
    float* out = (float*)d_out;

    cudaMemcpyToSymbolAsync(g_bias, bG, 32*sizeof(float), 0, cudaMemcpyDeviceToDevice, 0);

    float *dBias, *dP;
    __half *dXh, *dWh, *dYh, *dWoTh;
    cudaGetSymbolAddress((void**)&dWh,   g_Wh);
    cudaGetSymbolAddress((void**)&dBias, g_bias);
    cudaGetSymbolAddress((void**)&dP,    g_P);
    cudaGetSymbolAddress((void**)&dYh,   g_Yh);
    cudaGetSymbolAddress((void**)&dWoTh, g_WoTh);
    cudaGetSymbolAddress((void**)&dXh,   g_Xh);

    // pack + convert operands to fp16
    pack_weights<<<(PC*Dd/4 + 255)/256, 256>>>(
        (const float4*)wG, (const float4*)wK, (const float4*)wV, (const float4*)wQ);
    cvt_x<<<((NT*Dd/4) + 255)/256, 256>>>((const float4*)X, NT*Dd/4);
    transpose_wo<<<dim3(Dd/32, (H*DK)/32), dim3(32,8)>>>(wO);

    int gsmem = STAGES*STAGE_BYTES;   // 65536 B
    cudaFuncSetAttribute(mgemm<true>,  cudaFuncAttributeMaxDynamicSharedMemorySize, gsmem);
    cudaFuncSetAttribute(mgemm<false>, cudaFuncAttributeMaxDynamicSharedMemorySize, gsmem);

    // 1) fused projection GEMM (fp16 tensor cores, fp32 accum)
    mgemm<true><<<dim3((PC+127)/128, NT/128), 128, gsmem>>>(
        dXh, dWh, dP, NT, PC, Dd, dBias, 32);

    // 2) gates
    gate_combine<<<NT, 256>>>();

    // 3) scans
    scan_kernel<<<Nb*E*Lw, 128>>>(iK, iV);

    // 4) attention (packed f32x2)
    int smem_bytes = 2*WW*SST*sizeof(float);
    cudaFuncSetAttribute(attention_kernel, cudaFuncAttributeMaxDynamicSharedMemorySize, smem_bytes);
    attention_kernel<<<Nb*(T/TQ), 256, smem_bytes>>>();

    // 5) output projection
    mgemm<false><<<dim3(Dd/128, NT/128), 128, gsmem>>>(
        dYh, dWoTh, out, NT, Dd, H*DK, nullptr, 0);
}

// round 12
// speedup vs baseline: 1.4837x; 1.0282x over previous
#include <cuda_runtime.h>
#include <cuda_fp16.h>
#include <math.h>
#include <stdint.h>

// ---- problem constants ----
#define Nb   2
#define T    4096
#define Dd   1024
#define H    8
#define E    4
#define Lw   32
#define TC   128
#define DK   64
#define NT   (Nb*T)       // 8192
#define PC   1568         // 32 G + 512 K + 512 V + 512 Q
#define RLEN (Lw + T)     // 4128

#define TQ   32
#define WW   63
#define SST  260

#define STAGES 4
// one pipeline stage = 256 rows (128 A + 128 B) x 32 halves (64 B) = 16384 B
#define STAGE_BYTES 16384
#define STAGE_U32   4096

// ---- device scratch ----
__device__ __half  g_Wh[(size_t)PC*Dd];     // fp16 weights (concat)
__device__ float   g_bias[PC];
__device__ __half  g_Xh[(size_t)NT*Dd];     // fp16 X
__device__ float   g_P[(size_t)NT*PC];
__device__ float   g_A[Nb*E*T];
__device__ float   g_gK[(size_t)Nb*E*T*DK];
__device__ float   g_gV[(size_t)Nb*E*T*DK];
__device__ float   g_recK[(size_t)Nb*E*RLEN*DK];
__device__ float   g_recV[(size_t)Nb*E*RLEN*DK];
__device__ __half  g_Yh[(size_t)NT*H*DK];   // fp16 attention output
__device__ __half  g_WoTh[(size_t)Dd*H*DK]; // fp16 w_O^T

// ============================================================
// helpers
// ============================================================
__device__ __forceinline__ void mma_f16(float4& c,
    uint32_t a0, uint32_t a1, uint32_t a2, uint32_t a3,
    uint32_t b0, uint32_t b1)
{
    asm volatile("mma.sync.aligned.m16n8k16.row.col.f32.f16.f16.f32 "
        "{%0,%1,%2,%3}, {%4,%5,%6,%7}, {%8,%9}, {%0,%1,%2,%3};"
        : "+f"(c.x), "+f"(c.y), "+f"(c.z), "+f"(c.w)
        : "r"(a0), "r"(a1), "r"(a2), "r"(a3), "r"(b0), "r"(b1));
}

__device__ __forceinline__ void cp16(uint32_t dst, const void* src, int sz) {
    asm volatile("cp.async.cg.shared.global [%0], [%1], 16, %2;"
                 :: "r"(dst), "l"(src), "r"(sz));
}
__device__ __forceinline__ void cp_commit() { asm volatile("cp.async.commit_group;"); }
__device__ __forceinline__ void cp_wait2()  { asm volatile("cp.async.wait_group 2;"); }

// packed fp32x2 math (sm_100+ base ISA) — exact fp32 semantics, 2 lanes/op
__device__ __forceinline__ uint64_t pack2(float lo, float hi) {
    uint64_t r;
    asm("mov.b64 %0, {%1, %2};" : "=l"(r)
        : "r"(__float_as_uint(lo)), "r"(__float_as_uint(hi)));
    return r;
}
__device__ __forceinline__ void unpack2(uint64_t v, float& lo, float& hi) {
    uint32_t a, b;
    asm("mov.b64 {%0, %1}, %2;" : "=r"(a), "=r"(b) : "l"(v));
    lo = __uint_as_float(a); hi = __uint_as_float(b);
}
__device__ __forceinline__ uint64_t ffma2(uint64_t a, uint64_t b, uint64_t c) {
    uint64_t d;
    asm("fma.rn.f32x2 %0, %1, %2, %3;" : "=l"(d) : "l"(a), "l"(b), "l"(c));
    return d;
}

// ============================================================
// FP16 GEMM (NT): unchanged from round 11 (94.8us / 47.7% tensor)
// ============================================================
template<bool ACT>
__global__ __launch_bounds__(128, 2) void mgemm(
    const __half* __restrict__ A, const __half* __restrict__ B,
    float* __restrict__ C, int M, int Nn, int K,
    const float* __restrict__ bias, int act_cols)
{
    extern __shared__ __align__(16) __half hsm[];

    int tid  = threadIdx.x;
    int bm   = blockIdx.y, bn = blockIdx.x;
    int warp = tid >> 5, lane = tid & 31;
    int wm   = (warp >> 1) * 64;
    int wn   = (warp & 1) * 64;
    int gid  = lane >> 2, tig = lane & 3;

    uint32_t sbase = (uint32_t)__cvta_generic_to_shared(hsm);

    const __half* srcp[8];
    uint32_t dsto[8];
    int szs[8];
    #pragma unroll
    for (int j = 0; j < 8; ++j) {
        int i = j*128 + tid;
        int row = i >> 2, c = i & 3;
        bool isA = row < 128;
        int g  = isA ? (bm*128 + row) : (bn*128 + (row - 128));
        int sz = isA ? 16 : ((g < Nn) ? 16 : 0);
        srcp[j] = (isA ? A + (size_t)g*K
                       : B + (size_t)(sz ? g : 0)*K) + c*8;
        dsto[j] = row*64 + c*16;
        szs[j]  = sz;
    }

    auto stage = [&](int kt, int s) {
        uint32_t d = sbase + s*STAGE_BYTES;
        #pragma unroll
        for (int j = 0; j < 8; ++j)
            cp16(d + dsto[j], srcp[j] + kt*32, szs[j]);
        cp_commit();
    };

    float4 acc[4][8];
    #pragma unroll
    for (int i = 0; i < 4; ++i)
        #pragma unroll
        for (int j = 0; j < 8; ++j) acc[i][j] = make_float4(0.f,0.f,0.f,0.f);

    int nk = K / 32;
    stage(0, 0);
    stage(1, 1);
    stage(2, 2);

    const uint32_t* Hs = (const uint32_t*)hsm;

    for (int kt0 = 0; kt0 < nk; kt0 += 4) {
        #pragma unroll
        for (int u = 0; u < 4; ++u) {
            int kt = kt0 + u;
            cp_wait2();
            __syncthreads();

            const uint32_t* as = Hs + u*STAGE_U32;
            const uint32_t* bs = as + 128*16;

            uint4 alo[4], ahi[4], bf[8];
            #pragma unroll
            for (int mf = 0; mf < 4; ++mf) {
                alo[mf] = *(const uint4*)&as[(wm + mf*16 + gid    )*16 + tig*4];
                ahi[mf] = *(const uint4*)&as[(wm + mf*16 + gid + 8)*16 + tig*4];
            }
            #pragma unroll
            for (int nf = 0; nf < 8; ++nf)
                bf[nf] = *(const uint4*)&bs[(wn + nf*8 + gid)*16 + tig*4];

            #pragma unroll
            for (int mf = 0; mf < 4; ++mf)
                #pragma unroll
                for (int nf = 0; nf < 8; ++nf) {
                    mma_f16(acc[mf][nf], alo[mf].x, ahi[mf].x, alo[mf].y, ahi[mf].y,
                                         bf[nf].x, bf[nf].y);
                    mma_f16(acc[mf][nf], alo[mf].z, ahi[mf].z, alo[mf].w, ahi[mf].w,
                                         bf[nf].z, bf[nf].w);
                }

            int kn = kt + 3;
            if (kn < nk) stage(kn, (u + 3) & 3);
            else cp_commit();
        }
    }

    #pragma unroll
    for (int mf = 0; mf < 4; ++mf) {
        int row = bm*128 + wm + mf*16 + gid;
        #pragma unroll
        for (int nf = 0; nf < 8; ++nf) {
            int col = bn*128 + wn + nf*8 + tig*2;
            if (col < Nn) {
                float4 v = acc[mf][nf];
                if (ACT && col < act_cols) {
                    v.x = 1.f/(1.f + __expf(-(v.x + bias[col])));
                    v.y = 1.f/(1.f + __expf(-(v.y + bias[col+1])));
                    v.z = 1.f/(1.f + __expf(-(v.z + bias[col])));
                    v.w = 1.f/(1.f + __expf(-(v.w + bias[col+1])));
                }
                *(float2*)(C + (size_t)row*Nn + col)     = make_float2(v.x, v.y);
                *(float2*)(C + (size_t)(row+8)*Nn + col) = make_float2(v.z, v.w);
            }
        }
    }
}

// ============================================================
// fused weight pack + fp16 convert
// ============================================================
__global__ void pack_weights(const float4* __restrict__ wG,
                             const float4* __restrict__ wK,
                             const float4* __restrict__ wV,
                             const float4* __restrict__ wQ)
{
    int i = blockIdx.x*blockDim.x + threadIdx.x;
    if (i >= PC*Dd/4) return;
    int row = i / (Dd/4);
    int c4  = i - row*(Dd/4);
    float4 v;
    if (row < 32)        v = wG[row*(Dd/4) + c4];
    else if (row < 544)  v = wK[(row-32)*(Dd/4) + c4];
    else if (row < 1056) v = wV[(row-544)*(Dd/4) + c4];
    else                 v = wQ[(row-1056)*(Dd/4) + c4];
    __half2* o = (__half2*)(g_Wh + (size_t)i*4);
    o[0] = __floats2half2_rn(v.x, v.y);
    o[1] = __floats2half2_rn(v.z, v.w);
}

__global__ void cvt_x(const float4* __restrict__ X, int n4)
{
    int i = blockIdx.x*blockDim.x + threadIdx.x;
    if (i < n4) {
        float4 v = X[i];
        __half2* o = (__half2*)(g_Xh + (size_t)i*4);
        o[0] = __floats2half2_rn(v.x, v.y);
        o[1] = __floats2half2_rn(v.z, v.w);
    }
}

// ============================================================
// Gate combine
// ============================================================
__global__ __launch_bounds__(256) void gate_combine()
{
    int row = blockIdx.x;
    int n = row / T, t = row - n*T;
    __shared__ float sG[H*E];
    int tid = threadIdx.x;
    const float* Pr = g_P + (size_t)row*PC;
    if (tid < H*E) sG[tid] = Pr[tid];
    __syncthreads();
    if (tid < E) {
        float s = 0.f;
        #pragma unroll
        for (int h = 0; h < H; ++h) s += sG[h*E + tid];
        g_A[(n*E + tid)*T + t] = 1.f - fminf(s, 1.f);
    }
    int e = tid >> 6, d = tid & 63;
    float sk = 0.f, sv = 0.f;
    #pragma unroll
    for (int h = 0; h < H; ++h) {
        float g = sG[h*E + e];
        sk = fmaf(g, Pr[32  + h*64 + d], sk);
        sv = fmaf(g, Pr[544 + h*64 + d], sv);
    }
    size_t o = ((size_t)(n*E + e)*T + t)*DK + d;
    g_gK[o] = sk;
    g_gV[o] = sv;
}

// ============================================================
// Scan: prefetch distance 16 (two 8-groups in flight)
// ============================================================
__global__ __launch_bounds__(128) void scan_kernel(
    const float* __restrict__ initK, const float* __restrict__ initV)
{
    __shared__ float sa[TC];
    int b = blockIdx.x;
    int l = b % Lw, e = (b / Lw) % E, n = b / (Lw*E);
    int tid = threadIdx.x;
    bool isV = tid >= 64;
    int d = tid & 63;
    const float* init = isV ? initV : initK;
    const float* g    = isV ? g_gV  : g_gK;
    float*       rec  = isV ? g_recV : g_recK;

    size_t base = (size_t)(n*E + e);
    int t0 = l*TC;
    const float* Arow = g_A + base*T + t0;
    if (tid < TC) sa[tid] = Arow[tid];
    __syncthreads();

    float st = init[(e*Lw + l)*DK + d];
    rec[(base*RLEN + l)*DK + d] = st;
    const float* grow   = g   + (base*T   + t0)*(size_t)DK + d;
    float*       recrow = rec + (base*RLEN + Lw + t0)*(size_t)DK + d;

    float bufA[8], bufB[8];
    #pragma unroll
    for (int j = 0; j < 8; ++j) bufA[j] = grow[(size_t)j*DK];
    #pragma unroll
    for (int j = 0; j < 8; ++j) bufB[j] = grow[(size_t)(8+j)*DK];

    for (int c0 = 0; c0 < TC; c0 += 16) {
        float nA[8], nB[8];
        bool more = (c0 + 16 < TC);
        if (more) {
            #pragma unroll
            for (int j = 0; j < 8; ++j) nA[j] = grow[(size_t)(c0+16+j)*DK];
        }
        #pragma unroll
        for (int j = 0; j < 8; ++j) {
            st = fmaf(sa[c0+j], st, bufA[j]);
            recrow[(size_t)(c0+j)*DK] = st;
        }
        if (more) {
            #pragma unroll
            for (int j = 0; j < 8; ++j) nB[j] = grow[(size_t)(c0+24+j)*DK];
        }
        #pragma unroll
        for (int j = 0; j < 8; ++j) {
            st = fmaf(sa[c0+8+j], st, bufB[j]);
            recrow[(size_t)(c0+8+j)*DK] = st;
        }
        #pragma unroll
        for (int j = 0; j < 8; ++j) { bufA[j] = nA[j]; bufB[j] = nB[j]; }
    }
}

// ============================================================
// Attention: BRANCH-FREE softmax via norm-bound exponent shift.
// m = 0.125*|Q|*max||K||  >=  max(s); softmax invariant to shift,
// exp(s-m) in [e^-~40, 1] — no overflow, no meaningful underflow
// (clamped at -75 for pathological tails). Packed f32x2 math.
// ============================================================
extern __shared__ float sm_att[];

__global__ __launch_bounds__(256, 1) void attention_kernel()
{
    float* Ks = sm_att;
    float* Vs = sm_att + WW*SST;
    __shared__ int s_maxk;           // max sumsq(K) as ordered int (positive floats)
    int bid = blockIdx.x;
    int n    = bid / (T/TQ);
    int tile = bid % (T/TQ);
    int t0 = tile*TQ;
    int tid = threadIdx.x;

    if (tid == 0) s_maxk = 0;

    for (int i = tid; i < WW*E*16; i += 256) {
        int w   = i >> 6;
        int rem = i & 63;
        int e = rem >> 4, d4 = rem & 15;
        size_t go = (((size_t)(n*E + e))*RLEN + (1 + t0 + w))*DK + d4*4;
        float4 kv = *(const float4*)(g_recK + go);
        float4 vv = *(const float4*)(g_recV + go);
        int so = w*SST + e*64 + d4*4;
        *(float4*)(Ks + so) = kv;
        *(float4*)(Vs + so) = vv;
    }
    __syncthreads();

    // block-max of K sumsq (one thread per window position)
    if (tid < WW*E) {
        int w = tid >> 2, e = tid & 3;
        const float4* kp = (const float4*)(Ks + w*SST + e*64);
        float ss = 0.f;
        #pragma unroll
        for (int i = 0; i < 16; ++i) {
            float4 k4 = kp[i];
            ss = fmaf(k4.x,k4.x, fmaf(k4.y,k4.y, fmaf(k4.z,k4.z, fmaf(k4.w,k4.w, ss))));
        }
        atomicMax(&s_maxk, __float_as_int(ss));
    }

    int h = tid & 7, tq = tid >> 3;
    int t = t0 + tq;

    // Q as 32 packed f32x2 + |Q|^2
    uint64_t q2[32];
    float qss = 0.f;
    const ulonglong2* Qp2 = (const ulonglong2*)(g_P + (size_t)(n*T + t)*PC + 1056 + h*64);
    #pragma unroll
    for (int i = 0; i < 16; ++i) {
        ulonglong2 v = Qp2[i];
        q2[2*i]   = v.x;
        q2[2*i+1] = v.y;
        float a,b,c,d;
        unpack2(v.x, a, b); unpack2(v.y, c, d);
        qss = fmaf(a,a, fmaf(b,b, fmaf(c,c, fmaf(d,d, qss))));
    }
    __syncthreads();

    float m = 0.125f * sqrtf(qss) * sqrtf(__int_as_float(s_maxk));

    float sum = 0.f;
    uint64_t acc2[32];
    #pragma unroll
    for (int i = 0; i < 32; ++i) acc2[i] = 0ull;

    for (int e = 0; e < E; ++e) {
        for (int l = 0; l < Lw; ++l) {
            int base = (tq + l)*SST + e*64;
            const ulonglong2* kp2 = (const ulonglong2*)(Ks + base);
            uint64_t sa = 0ull, sb = 0ull, sc = 0ull, sd = 0ull;
            #pragma unroll
            for (int i = 0; i < 8; ++i) {
                ulonglong2 k0 = kp2[2*i];
                ulonglong2 k1 = kp2[2*i+1];
                sa = ffma2(q2[4*i],   k0.x, sa);
                sb = ffma2(q2[4*i+1], k0.y, sb);
                sc = ffma2(q2[4*i+2], k1.x, sc);
                sd = ffma2(q2[4*i+3], k1.y, sd);
            }
            float a0, a1, b0, b1, c0, c1, d0, d1;
            unpack2(sa, a0, a1); unpack2(sb, b0, b1);
            unpack2(sc, c0, c1); unpack2(sd, d0, d1);
            float s = (((a0 + a1) + (b0 + b1)) + ((c0 + c1) + (d0 + d1))) * 0.125f;

            float p = __expf(fmaxf(s - m, -75.f));
            sum += p;
            uint64_t p2 = pack2(p, p);
            const ulonglong2* vp2 = (const ulonglong2*)(Vs + base);
            #pragma unroll
            for (int i = 0; i < 16; ++i) {
                ulonglong2 v = vp2[i];
                acc2[2*i]   = ffma2(p2, v.x, acc2[2*i]);
                acc2[2*i+1] = ffma2(p2, v.y, acc2[2*i+1]);
            }
        }
    }

    float inv = 1.f / sum;
    __half2* Yp = (__half2*)(g_Yh + (size_t)(n*T + t)*(H*DK) + h*64);
    #pragma unroll
    for (int i = 0; i < 32; ++i) {
        float lo, hi;
        unpack2(acc2[i], lo, hi);
        Yp[i] = __floats2half2_rn(lo*inv, hi*inv);
    }
}

// ============================================================
// w_O transpose: (512,1024) -> (1024,512), fp16 output
// ============================================================
__global__ void transpose_wo(const float* __restrict__ src)
{
    __shared__ float tile[32][33];
    int tx = threadIdx.x, ty = threadIdx.y;
    int x = blockIdx.x*32 + tx;
    int y = blockIdx.y*32 + ty;
    #pragma unroll
    for (int i = 0; i < 32; i += 8)
        tile[ty+i][tx] = src[(size_t)(y+i)*Dd + x];
    __syncthreads();
    int x2 = blockIdx.y*32 + tx;
    int y2 = blockIdx.x*32 + ty;
    #pragma unroll
    for (int i = 0; i < 32; i += 8)
        g_WoTh[(size_t)(y2+i)*(H*DK) + x2] = __float2half_rn(tile[tx][ty+i]);
}

// ============================================================
extern "C" void kernel_launch(void* const* d_in, const int* in_sizes, int n_in,
                              void* d_out, int out_size)
{
    const float* X  = (const float*)d_in[0];
    const float* wG = (const float*)d_in[1];
    const float* bG = (const float*)d_in[2];
    const float* wK = (const float*)d_in[3];
    const float* wV = (const float*)d_in[4];
    const float* wQ = (const float*)d_in[5];
    const float* wO = (const float*)d_in[6];
    const float* iK = (const float*)d_in[7];
    const float* iV = (const float*)d_in[8];
    float* out = (float*)d_out;

    cudaMemcpyToSymbolAsync(g_bias, bG, 32*sizeof(float), 0, cudaMemcpyDeviceToDevice, 0);

    float *dBias, *dP;
    __half *dXh, *dWh, *dYh, *dWoTh;
    cudaGetSymbolAddress((void**)&dWh,   g_Wh);
    cudaGetSymbolAddress((void**)&dBias, g_bias);
    cudaGetSymbolAddress((void**)&dP,    g_P);
    cudaGetSymbolAddress((void**)&dYh,   g_Yh);
    cudaGetSymbolAddress((void**)&dWoTh, g_WoTh);
    cudaGetSymbolAddress((void**)&dXh,   g_Xh);

    // pack + convert operands to fp16
    pack_weights<<<(PC*Dd/4 + 255)/256, 256>>>(
        (const float4*)wG, (const float4*)wK, (const float4*)wV, (const float4*)wQ);
    cvt_x<<<((NT*Dd/4) + 255)/256, 256>>>((const float4*)X, NT*Dd/4);
    transpose_wo<<<dim3(Dd/32, (H*DK)/32), dim3(32,8)>>>(wO);

    int gsmem = STAGES*STAGE_BYTES;   // 65536 B
    cudaFuncSetAttribute(mgemm<true>,  cudaFuncAttributeMaxDynamicSharedMemorySize, gsmem);
    cudaFuncSetAttribute(mgemm<false>, cudaFuncAttributeMaxDynamicSharedMemorySize, gsmem);

    // 1) fused projection GEMM (fp16 tensor cores, fp32 accum)
    mgemm<true><<<dim3((PC+127)/128, NT/128), 128, gsmem>>>(
        dXh, dWh, dP, NT, PC, Dd, dBias, 32);

    // 2) gates
    gate_combine<<<NT, 256>>>();

    // 3) scans
    scan_kernel<<<Nb*E*Lw, 128>>>(iK, iV);

    // 4) attention (branch-free softmax, packed f32x2)
    int smem_bytes = 2*WW*SST*sizeof(float);
    cudaFuncSetAttribute(attention_kernel, cudaFuncAttributeMaxDynamicSharedMemorySize, smem_bytes);
    attention_kernel<<<Nb*(T/TQ), 256, smem_bytes>>>();

    // 5) output projection
    mgemm<false><<<dim3(Dd/128, NT/128), 128, gsmem>>>(
        dYh, dWoTh, out, NT, Dd, H*DK, nullptr, 0);
}